// round 11
// baseline (speedup 1.0000x reference)
#include <cuda_runtime.h>
#include <cuda_fp16.h>

#define BB 8
#define NN 1024
#define DD 128

// ---------------- scratch (device globals; no allocation allowed) ----------
__device__ float g_v[BB * NN * DD];
__device__ float g_k[BB * NN * DD];
__device__ float g_q[BB * NN * DD];
__device__ float g_o[BB * NN * DD];
__device__ __half g_vh[BB * NN * DD];
__device__ __half g_kh[BB * NN * DD];
__device__ __half g_qh[BB * NN * DD];   // pre-scaled by 1/sqrt(D)
__device__ float g_kpe[NN * NN];
__device__ float g_vpe4[4 * NN * DD];   // 4 m-chunk partials

// ---------------- asm helpers ----------------------------------------------
__device__ __forceinline__ unsigned smem_u32(const void* p) {
    unsigned a;
    asm("{ .reg .u64 t; cvta.to.shared.u64 t, %1; cvt.u32.u64 %0, t; }"
        : "=r"(a) : "l"(p));
    return a;
}
__device__ __forceinline__ void ldsm_x4(unsigned& a0, unsigned& a1,
                                        unsigned& a2, unsigned& a3, unsigned addr) {
    asm volatile("ldmatrix.sync.aligned.m8n8.x4.shared.b16 {%0,%1,%2,%3}, [%4];"
                 : "=r"(a0), "=r"(a1), "=r"(a2), "=r"(a3) : "r"(addr));
}
__device__ __forceinline__ void ldsm_x2(unsigned& b0, unsigned& b1, unsigned addr) {
    asm volatile("ldmatrix.sync.aligned.m8n8.x2.shared.b16 {%0,%1}, [%2];"
                 : "=r"(b0), "=r"(b1) : "r"(addr));
}
__device__ __forceinline__ void ldsm_x2t(unsigned& b0, unsigned& b1, unsigned addr) {
    asm volatile("ldmatrix.sync.aligned.m8n8.x2.trans.shared.b16 {%0,%1}, [%2];"
                 : "=r"(b0), "=r"(b1) : "r"(addr));
}
__device__ __forceinline__ void mma_f16(float d[4], const unsigned a[4],
                                        const unsigned b[2]) {
    asm("mma.sync.aligned.m16n8k16.row.col.f32.f16.f16.f32 "
        "{%0,%1,%2,%3}, {%4,%5,%6,%7}, {%8,%9}, {%0,%1,%2,%3};"
        : "+f"(d[0]), "+f"(d[1]), "+f"(d[2]), "+f"(d[3])
        : "r"(a[0]), "r"(a[1]), "r"(a[2]), "r"(a[3]), "r"(b[0]), "r"(b[1]));
}
__device__ __forceinline__ void cp16(unsigned dst, const void* src) {
    asm volatile("cp.async.cg.shared.global [%0], [%1], 16;"
                 :: "r"(dst), "l"(src));
}
__device__ __forceinline__ float4 ldcs4(const float4* p) {
    float4 v;
    asm volatile("ld.global.cs.v4.f32 {%0,%1,%2,%3}, [%4];"
                 : "=f"(v.x), "=f"(v.y), "=f"(v.z), "=f"(v.w) : "l"(p));
    return v;
}

// ---------------- kpe[n,m] = sum_d keys_pos_enc[n,m,d] ---------------------
// warp-per-32-rows; 2x8-row groups interleaved so 16 loads are in flight
// before the shuffle phases. Streaming loads (read-once).
__global__ __launch_bounds__(256) void kpe_kernel(const float* __restrict__ kp) {
    int gwarp = (blockIdx.x * 256 + threadIdx.x) >> 5;
    int lane = threadIdx.x & 31;
#pragma unroll
    for (int gp = 0; gp < 2; gp++) {
        size_t rowA = (size_t)gwarp * 32 + gp * 16;
        const float4* pA = reinterpret_cast<const float4*>(kp) + rowA * 32 + lane;
        const float4* pB = pA + 8 * 32;
        float sa[8], sb[8];
#pragma unroll
        for (int i = 0; i < 8; i++) {
            float4 v = ldcs4(pA + i * 32);
            sa[i] = (v.x + v.y) + (v.z + v.w);
        }
#pragma unroll
        for (int i = 0; i < 8; i++) {
            float4 v = ldcs4(pB + i * 32);
            sb[i] = (v.x + v.y) + (v.z + v.w);
        }
#pragma unroll
        for (int i = 0; i < 8; i++) {
#pragma unroll
            for (int o = 16; o >= 1; o >>= 1) {
                sa[i] += __shfl_xor_sync(0xffffffffu, sa[i], o);
                sb[i] += __shfl_xor_sync(0xffffffffu, sb[i], o);
            }
        }
        float outA = 0.f, outB = 0.f;
#pragma unroll
        for (int i = 0; i < 8; i++)
            if (lane == i) { outA = sa[i]; outB = sb[i]; }
        if (lane < 8) {
            g_kpe[rowA + lane] = outA;
            g_kpe[rowA + 8 + lane] = outB;
        }
    }
}

// ---------------- vpe4[h][n][d] = sum_{m in chunk h} values_pos_enc[n,m,d] --
// grid (512, 4): n = n_base + bx, m-chunk h = by (256 rows each). 2048 CTAs
// per launch -> tail quantization ~7%. 8 independent acc chains, streaming.
__global__ __launch_bounds__(256) void vpe_kernel(const float* __restrict__ vp,
                                                  int n_base) {
    __shared__ float4 red[8][32];
    int n = n_base + blockIdx.x;
    int h = blockIdx.y;
    int g = threadIdx.x >> 5, lane = threadIdx.x & 31;
    const float4* base = reinterpret_cast<const float4*>(vp + (size_t)n * NN * DD)
                         + (size_t)h * 256 * 32;
    float4 acc[8];
#pragma unroll
    for (int i = 0; i < 8; i++) acc[i] = make_float4(0.f, 0.f, 0.f, 0.f);
#pragma unroll
    for (int m = 0; m < 256; m += 64) {
#pragma unroll
        for (int i = 0; i < 8; i++) {
            float4 v = ldcs4(base + (m + g + i * 8) * 32 + lane);
            acc[i].x += v.x; acc[i].y += v.y; acc[i].z += v.z; acc[i].w += v.w;
        }
    }
#pragma unroll
    for (int i = 1; i < 8; i++) {
        acc[0].x += acc[i].x; acc[0].y += acc[i].y;
        acc[0].z += acc[i].z; acc[0].w += acc[i].w;
    }
    red[g][lane] = acc[0];
    __syncthreads();
    if (g == 0) {
        float4 a = red[0][lane];
#pragma unroll
        for (int i = 1; i < 8; i++) {
            float4 b = red[i][lane];
            a.x += b.x; a.y += b.y; a.z += b.z; a.w += b.w;
        }
        reinterpret_cast<float4*>(g_vpe4 + ((size_t)h * NN + n) * DD)[lane] = a;
    }
}

// ---------------- fused projection: v = X Wv^T; k = v Wk^T; q = v Wq^T -----
#define FPROJ_SMEM ((64 * 132 + 64 * 132 + 128 * 132) * 4)

__device__ __forceinline__ void gemm_64x128(const float* __restrict__ sA,
                                            const float* __restrict__ sWt,
                                            int ty, int tx, float acc[4][8]) {
#pragma unroll
    for (int i = 0; i < 4; i++)
#pragma unroll
        for (int j = 0; j < 8; j++) acc[i][j] = 0.f;
    for (int kk = 0; kk < 128; kk += 4) {
        float4 a[4];
#pragma unroll
        for (int i = 0; i < 4; i++)
            a[i] = *reinterpret_cast<const float4*>(sA + (ty * 4 + i) * 132 + kk);
#pragma unroll
        for (int t = 0; t < 4; t++) {
            float4 b0 = *reinterpret_cast<const float4*>(sWt + (kk + t) * 132 + tx * 8);
            float4 b1 = *reinterpret_cast<const float4*>(sWt + (kk + t) * 132 + tx * 8 + 4);
#pragma unroll
            for (int i = 0; i < 4; i++) {
                float aa = reinterpret_cast<const float*>(&a[i])[t];
                acc[i][0] += aa * b0.x; acc[i][1] += aa * b0.y;
                acc[i][2] += aa * b0.z; acc[i][3] += aa * b0.w;
                acc[i][4] += aa * b1.x; acc[i][5] += aa * b1.y;
                acc[i][6] += aa * b1.z; acc[i][7] += aa * b1.w;
            }
        }
    }
}

__device__ __forceinline__ void load_wt(const float* __restrict__ W,
                                        float* __restrict__ sWt, int tid) {
    for (int it = tid; it < 128 * 32; it += 256) {
        int o = it >> 5, e4 = it & 31;
        float4 v = *reinterpret_cast<const float4*>(W + o * DD + e4 * 4);
        sWt[(e4 * 4 + 0) * 132 + o] = v.x;
        sWt[(e4 * 4 + 1) * 132 + o] = v.y;
        sWt[(e4 * 4 + 2) * 132 + o] = v.z;
        sWt[(e4 * 4 + 3) * 132 + o] = v.w;
    }
}

__device__ __forceinline__ void store_half8(__half* dst, const float* a, float sc) {
#pragma unroll
    for (int j = 0; j < 4; j++) {
        __half2 h = __floats2half2_rn(a[2 * j] * sc, a[2 * j + 1] * sc);
        *reinterpret_cast<__half2*>(dst + 2 * j) = h;
    }
}

__global__ __launch_bounds__(256) void proj_fused_kernel(
    const float* __restrict__ X, const float* __restrict__ Wv,
    const float* __restrict__ Wk, const float* __restrict__ Wq) {
    extern __shared__ float sm[];
    float* sX = sm;
    float* sV = sm + 64 * 132;
    float* sWt = sm + 2 * 64 * 132;
    const float inv_s = 0.088388347648318447f;

    int tid = threadIdx.x;
    int row0 = blockIdx.x * 64;
    int ty = tid >> 4, tx = tid & 15;
    float acc[4][8];

    for (int it = tid; it < 64 * 32; it += 256) {
        int r = it >> 5, c4 = it & 31;
        float4 v = *reinterpret_cast<const float4*>(X + (size_t)(row0 + r) * DD + c4 * 4);
        *reinterpret_cast<float4*>(sX + r * 132 + c4 * 4) = v;
    }
    load_wt(Wv, sWt, tid);
    __syncthreads();

    gemm_64x128(sX, sWt, ty, tx, acc);
    __syncthreads();
#pragma unroll
    for (int i = 0; i < 4; i++) {
        int r = ty * 4 + i;
        size_t go = (size_t)(row0 + r) * DD + tx * 8;
        float4 lo = make_float4(acc[i][0], acc[i][1], acc[i][2], acc[i][3]);
        float4 hi = make_float4(acc[i][4], acc[i][5], acc[i][6], acc[i][7]);
        *reinterpret_cast<float4*>(sV + r * 132 + tx * 8) = lo;
        *reinterpret_cast<float4*>(sV + r * 132 + tx * 8 + 4) = hi;
        *reinterpret_cast<float4*>(g_v + go) = lo;
        *reinterpret_cast<float4*>(g_v + go + 4) = hi;
        store_half8(g_vh + go, acc[i], 1.0f);
    }
    load_wt(Wk, sWt, tid);
    __syncthreads();

    gemm_64x128(sV, sWt, ty, tx, acc);
#pragma unroll
    for (int i = 0; i < 4; i++) {
        size_t go = (size_t)(row0 + ty * 4 + i) * DD + tx * 8;
        *reinterpret_cast<float4*>(g_k + go) = make_float4(acc[i][0], acc[i][1], acc[i][2], acc[i][3]);
        *reinterpret_cast<float4*>(g_k + go + 4) = make_float4(acc[i][4], acc[i][5], acc[i][6], acc[i][7]);
        store_half8(g_kh + go, acc[i], 1.0f);
    }
    __syncthreads();
    load_wt(Wq, sWt, tid);
    __syncthreads();

    gemm_64x128(sV, sWt, ty, tx, acc);
#pragma unroll
    for (int i = 0; i < 4; i++) {
        size_t go = (size_t)(row0 + ty * 4 + i) * DD + tx * 8;
        *reinterpret_cast<float4*>(g_q + go) = make_float4(acc[i][0], acc[i][1], acc[i][2], acc[i][3]);
        *reinterpret_cast<float4*>(g_q + go + 4) = make_float4(acc[i][4], acc[i][5], acc[i][6], acc[i][7]);
        store_half8(g_qh + go, acc[i], inv_s);   // pre-scaled q
    }
}

// ---------------- fp16 tensor-core flash attention (round-7, known-good) ----
#define HQS 136
#define HKS 136
#define HVS 136
#define HPS 72
#define ATTN_SMEM ((64*HQS + 2*64*HKS + 2*64*HVS + 64*HPS) * 2 + 512 * 4)

__global__ __launch_bounds__(256) void attn_kernel(const int* __restrict__ mask) {
    extern __shared__ __half hsm[];
    __half* sQ = hsm;                         // 64 x 136
    __half* sK = sQ + 64 * HQS;               // 2 x 64 x 136
    __half* sV = sK + 2 * 64 * HKS;           // 2 x 64 x 136
    __half* sP = sV + 2 * 64 * HVS;           // 64 x 72
    float* sM = reinterpret_cast<float*>(sP + 64 * HPS);  // 2 x 64
    float* sL = sM + 128;                     // 2 x 64
    float* sRMax = sL + 128;                  // 64 x 2
    float* sRSum = sRMax + 128;               // 64 x 2

    int tid = threadIdx.x;
    int b = blockIdx.y;
    int n0 = blockIdx.x * 64;
    int w = tid >> 5, lane = tid & 31;
    int mi = w & 3, ni = w >> 2;
    int qg = lane >> 2, qt = lane & 3;
    const float inv_s = 0.088388347648318447f;

    unsigned uQ = smem_u32(sQ);
    unsigned uK = smem_u32(sK);
    unsigned uV = smem_u32(sV);
    unsigned uP = smem_u32(sP);
    int l15 = lane & 15, l7 = lane & 7;

    // ---- load Q tile (fp16, already pre-scaled) ----
    for (int it = tid; it < 64 * 16; it += 256) {
        int r = it >> 4, c8 = it & 15;
        uint4 v = *reinterpret_cast<const uint4*>(
            g_qh + ((size_t)(b * NN + n0 + r)) * DD + c8 * 8);
        *reinterpret_cast<uint4*>(sQ + r * HQS + c8 * 8) = v;
    }
    if (tid < 64) { sM[tid] = -1e30f; sL[tid] = 0.f; }

    // ---- prologue: cp.async tile 0 into buffer 0 ----
    {
        const __half* kb = g_kh + ((size_t)(b * NN)) * DD;
        const __half* vb = g_vh + ((size_t)(b * NN)) * DD;
        for (int it = tid; it < 1024; it += 256) {
            int r = it >> 4, c16 = it & 15;
            cp16(uK + (r * HKS + c16 * 8) * 2, kb + r * DD + c16 * 8);
            cp16(uV + (r * HVS + c16 * 8) * 2, vb + r * DD + c16 * 8);
        }
        asm volatile("cp.async.commit_group;");
    }

    int lr0 = mi * 16 + qg, lr1 = lr0 + 8;

    float acc_o[8][4];
#pragma unroll
    for (int i = 0; i < 8; i++)
#pragma unroll
        for (int j = 0; j < 4; j++) acc_o[i][j] = 0.f;

    for (int t = 0; t < 16; t++) {
        int p = t & 1;
        int m0 = t * 64;
        unsigned uKb = uK + p * (64 * HKS * 2);
        unsigned uVb = uV + p * (64 * HVS * 2);

        // prefetch tile t+1 into other buffer, then wait for tile t
        if (t < 15) {
            int q2 = 1 - p;
            const __half* kb = g_kh + ((size_t)(b * NN + m0 + 64)) * DD;
            const __half* vb = g_vh + ((size_t)(b * NN + m0 + 64)) * DD;
            unsigned dK = uK + q2 * (64 * HKS * 2);
            unsigned dV = uV + q2 * (64 * HVS * 2);
            for (int it = tid; it < 1024; it += 256) {
                int r = it >> 4, c16 = it & 15;
                cp16(dK + (r * HKS + c16 * 8) * 2, kb + r * DD + c16 * 8);
                cp16(dV + (r * HVS + c16 * 8) * 2, vb + r * DD + c16 * 8);
            }
            asm volatile("cp.async.commit_group;");
            asm volatile("cp.async.wait_group 1;");
        } else {
            asm volatile("cp.async.wait_group 0;");
        }
        __syncthreads();   // tile t K/V visible; prior tile's sP/sM/sL reads done

        // ---- prefetch kpe/mask rows (overlaps S mma) ----
        const float* kp0 = g_kpe + (size_t)(n0 + lr0) * NN + m0 + ni * 32;
        const float* kp1 = g_kpe + (size_t)(n0 + lr1) * NN + m0 + ni * 32;
        const int* mr0 = mask + ((size_t)b * NN + n0 + lr0) * NN + m0 + ni * 32;
        const int* mr1 = mask + ((size_t)b * NN + n0 + lr1) * NN + m0 + ni * 32;
        float2 kv0[4], kv1[4];
        int2 mv0[4], mv1[4];
#pragma unroll
        for (int nt = 0; nt < 4; nt++) {
            int c = nt * 8 + 2 * qt;
            kv0[nt] = *reinterpret_cast<const float2*>(kp0 + c);
            kv1[nt] = *reinterpret_cast<const float2*>(kp1 + c);
            mv0[nt] = *reinterpret_cast<const int2*>(mr0 + c);
            mv1[nt] = *reinterpret_cast<const int2*>(mr1 + c);
        }

        // ---- S = Q K^T : warp tile 16x32, fp16 m16n8k16 ----
        float acc_s[4][4];
#pragma unroll
        for (int i = 0; i < 4; i++)
#pragma unroll
            for (int j = 0; j < 4; j++) acc_s[i][j] = 0.f;
#pragma unroll
        for (int ks = 0; ks < 8; ks++) {
            unsigned a[4];
            ldsm_x4(a[0], a[1], a[2], a[3],
                    uQ + ((mi * 16 + l15) * HQS + ks * 16 + (lane >> 4) * 8) * 2);
#pragma unroll
            for (int nt = 0; nt < 4; nt++) {
                unsigned bf[2];
                ldsm_x2(bf[0], bf[1],
                        uKb + ((ni * 32 + nt * 8 + l7) * HKS + ks * 16 +
                               ((lane >> 3) & 1) * 8) * 2);
                mma_f16(acc_s[nt], a, bf);
            }
        }

        // ---- + kpe/sqrt(D), mask; segment max ----
        float lmax0 = -1e30f, lmax1 = -1e30f;
#pragma unroll
        for (int nt = 0; nt < 4; nt++) {
            float e00 = acc_s[nt][0] + kv0[nt].x * inv_s; if (mv0[nt].x == 0) e00 = -1e30f;
            float e01 = acc_s[nt][1] + kv0[nt].y * inv_s; if (mv0[nt].y == 0) e01 = -1e30f;
            acc_s[nt][0] = e00; acc_s[nt][1] = e01;
            lmax0 = fmaxf(lmax0, fmaxf(e00, e01));
            float e10 = acc_s[nt][2] + kv1[nt].x * inv_s; if (mv1[nt].x == 0) e10 = -1e30f;
            float e11 = acc_s[nt][3] + kv1[nt].y * inv_s; if (mv1[nt].y == 0) e11 = -1e30f;
            acc_s[nt][2] = e10; acc_s[nt][3] = e11;
            lmax1 = fmaxf(lmax1, fmaxf(e10, e11));
        }
        lmax0 = fmaxf(lmax0, __shfl_xor_sync(0xffffffffu, lmax0, 1));
        lmax0 = fmaxf(lmax0, __shfl_xor_sync(0xffffffffu, lmax0, 2));
        lmax1 = fmaxf(lmax1, __shfl_xor_sync(0xffffffffu, lmax1, 1));
        lmax1 = fmaxf(lmax1, __shfl_xor_sync(0xffffffffu, lmax1, 2));
        if (qt == 0) {
            sRMax[lr0 * 2 + ni] = lmax0;
            sRMax[lr1 * 2 + ni] = lmax1;
        }
        __syncthreads();

        // ---- online softmax; write P (fp16) ----
        float mo0 = sM[p * 64 + lr0], mo1 = sM[p * 64 + lr1];
        float mn0 = fmaxf(mo0, fmaxf(sRMax[lr0 * 2], sRMax[lr0 * 2 + 1]));
        float mn1 = fmaxf(mo1, fmaxf(sRMax[lr1 * 2], sRMax[lr1 * 2 + 1]));
        float f0 = __expf(mo0 - mn0), f1 = __expf(mo1 - mn1);
        float ls0 = 0.f, ls1 = 0.f;
#pragma unroll
        for (int nt = 0; nt < 4; nt++) {
            int c = ni * 32 + nt * 8 + 2 * qt;
            float p00 = (acc_s[nt][0] < -5e29f) ? 0.f : __expf(acc_s[nt][0] - mn0);
            float p01 = (acc_s[nt][1] < -5e29f) ? 0.f : __expf(acc_s[nt][1] - mn0);
            *reinterpret_cast<__half2*>(sP + lr0 * HPS + c) = __floats2half2_rn(p00, p01);
            ls0 += p00 + p01;
            float p10 = (acc_s[nt][2] < -5e29f) ? 0.f : __expf(acc_s[nt][2] - mn1);
            float p11 = (acc_s[nt][3] < -5e29f) ? 0.f : __expf(acc_s[nt][3] - mn1);
            *reinterpret_cast<__half2*>(sP + lr1 * HPS + c) = __floats2half2_rn(p10, p11);
            ls1 += p10 + p11;
        }
        ls0 += __shfl_xor_sync(0xffffffffu, ls0, 1);
        ls0 += __shfl_xor_sync(0xffffffffu, ls0, 2);
        ls1 += __shfl_xor_sync(0xffffffffu, ls1, 1);
        ls1 += __shfl_xor_sync(0xffffffffu, ls1, 2);
        if (qt == 0) {
            sRSum[lr0 * 2 + ni] = ls0;
            sRSum[lr1 * 2 + ni] = ls1;
        }
        // rescale O accumulators
#pragma unroll
        for (int nt = 0; nt < 8; nt++) {
            acc_o[nt][0] *= f0; acc_o[nt][1] *= f0;
            acc_o[nt][2] *= f1; acc_o[nt][3] *= f1;
        }
        __syncthreads();  // sP + sRSum complete

        if (ni == 0 && qt == 0) {
            int q2 = 1 - p;
            sM[q2 * 64 + lr0] = mn0;
            sL[q2 * 64 + lr0] = sL[p * 64 + lr0] * f0 + sRSum[lr0 * 2] + sRSum[lr0 * 2 + 1];
            sM[q2 * 64 + lr1] = mn1;
            sL[q2 * 64 + lr1] = sL[p * 64 + lr1] * f1 + sRSum[lr1 * 2] + sRSum[lr1 * 2 + 1];
        }

        // ---- O += P V : warp tile 16x64, fp16 m16n8k16, V via ldmatrix.trans ----
#pragma unroll
        for (int ks = 0; ks < 4; ks++) {
            unsigned a[4];
            ldsm_x4(a[0], a[1], a[2], a[3],
                    uP + ((mi * 16 + l15) * HPS + ks * 16 + (lane >> 4) * 8) * 2);
#pragma unroll
            for (int nt = 0; nt < 8; nt++) {
                unsigned bf[2];
                ldsm_x2t(bf[0], bf[1],
                         uVb + ((ks * 16 + l15) * HVS + ni * 64 + nt * 8) * 2);
                mma_f16(acc_o[nt], a, bf);
            }
        }
    }

    __syncthreads();  // final sM/sL (parity 0 after t=15) visible
    float il0 = 1.0f / sL[lr0];
    float il1 = 1.0f / sL[lr1];
    float* o0 = g_o + ((size_t)(b * NN + n0 + lr0)) * DD;
    float* o1 = g_o + ((size_t)(b * NN + n0 + lr1)) * DD;
#pragma unroll
    for (int nt = 0; nt < 8; nt++) {
        int c = ni * 64 + nt * 8 + 2 * qt;
        *reinterpret_cast<float2*>(o0 + c) =
            make_float2(acc_o[nt][0] * il0, acc_o[nt][1] * il0);
        *reinterpret_cast<float2*>(o1 + c) =
            make_float2(acc_o[nt][2] * il1, acc_o[nt][3] * il1);
    }
}

// ---------------- epilogue: out = LN(O + sum_h vpe4[h]) + v ------------------
__global__ __launch_bounds__(256) void epi_kernel(
    const float* __restrict__ gamma, const float* __restrict__ beta,
    float* __restrict__ out, int n_off) {
    int tid = threadIdx.x;
    int b = blockIdx.y;
    int n = n_off + blockIdx.x * 64 + (tid >> 2);
    int part = tid & 3;

    const float* orow = g_o + ((size_t)(b * NN + n)) * DD;
    const float* v0 = g_vpe4 + (size_t)(0 * NN + n) * DD;
    const float* v1 = g_vpe4 + (size_t)(1 * NN + n) * DD;
    const float* v2 = g_vpe4 + (size_t)(2 * NN + n) * DD;
    const float* v3 = g_vpe4 + (size_t)(3 * NN + n) * DD;
    float x[32];
    float sum = 0.f, sq = 0.f;
#pragma unroll
    for (int u = 0; u < 32; u += 4) {
        int d = part * 32 + u;
        float4 o4 = *reinterpret_cast<const float4*>(orow + d);
        float4 p0 = *reinterpret_cast<const float4*>(v0 + d);
        float4 p1 = *reinterpret_cast<const float4*>(v1 + d);
        float4 p2 = *reinterpret_cast<const float4*>(v2 + d);
        float4 p3 = *reinterpret_cast<const float4*>(v3 + d);
        float4 v;
        v.x = o4.x + ((p0.x + p1.x) + (p2.x + p3.x));
        v.y = o4.y + ((p0.y + p1.y) + (p2.y + p3.y));
        v.z = o4.z + ((p0.z + p1.z) + (p2.z + p3.z));
        v.w = o4.w + ((p0.w + p1.w) + (p2.w + p3.w));
        x[u] = v.x; x[u + 1] = v.y; x[u + 2] = v.z; x[u + 3] = v.w;
        sum += v.x + v.y + v.z + v.w;
        sq += v.x * v.x + v.y * v.y + v.z * v.z + v.w * v.w;
    }
#pragma unroll
    for (int o = 1; o <= 2; o <<= 1) {
        sum += __shfl_xor_sync(0xffffffffu, sum, o);
        sq += __shfl_xor_sync(0xffffffffu, sq, o);
    }
    float mu = sum * (1.f / 128.f);
    float var = sq * (1.f / 128.f) - mu * mu;
    float rstd = rsqrtf(var + 1e-5f);
    const float* gvr = g_v + ((size_t)(b * NN + n)) * DD;
    float* orow_out = out + ((size_t)(b * NN + n)) * DD;
#pragma unroll
    for (int u = 0; u < 32; u += 4) {
        int d = part * 32 + u;
        float4 gm = *reinterpret_cast<const float4*>(gamma + d);
        float4 bt = *reinterpret_cast<const float4*>(beta + d);
        float4 vv = *reinterpret_cast<const float4*>(gvr + d);
        float4 r4;
        r4.x = (x[u] - mu) * rstd * gm.x + bt.x + vv.x;
        r4.y = (x[u + 1] - mu) * rstd * gm.y + bt.y + vv.y;
        r4.z = (x[u + 2] - mu) * rstd * gm.z + bt.z + vv.z;
        r4.w = (x[u + 3] - mu) * rstd * gm.w + bt.w + vv.w;
        *reinterpret_cast<float4*>(orow_out + d) = r4;
    }
}

// ---------------- launch ---------------------------------------------------
extern "C" void kernel_launch(void* const* d_in, const int* in_sizes, int n_in,
                              void* d_out, int out_size) {
    const float* values = (const float*)d_in[0];
    const int* mask = (const int*)d_in[3];
    const float* vpe = (const float*)d_in[4];
    const float* kpe = (const float*)d_in[5];
    const float* Wv = (const float*)d_in[6];
    const float* Wk = (const float*)d_in[7];
    const float* Wq = (const float*)d_in[8];
    const float* ln_gamma = (const float*)d_in[9];
    const float* ln_beta = (const float*)d_in[10];
    float* out = (float*)d_out;

    static cudaStream_t s2 = nullptr;
    static cudaEvent_t ev_fork = nullptr, ev_kpe = nullptr,
                       ev_vA = nullptr, ev_vB = nullptr;
    if (!s2) {
        int lo, hi;
        cudaDeviceGetStreamPriorityRange(&lo, &hi);
        cudaStreamCreateWithPriority(&s2, cudaStreamNonBlocking, hi);
        cudaEventCreateWithFlags(&ev_fork, cudaEventDisableTiming);
        cudaEventCreateWithFlags(&ev_kpe, cudaEventDisableTiming);
        cudaEventCreateWithFlags(&ev_vA, cudaEventDisableTiming);
        cudaEventCreateWithFlags(&ev_vB, cudaEventDisableTiming);
        cudaFuncSetAttribute(proj_fused_kernel,
                             cudaFuncAttributeMaxDynamicSharedMemorySize, FPROJ_SMEM);
        cudaFuncSetAttribute(attn_kernel,
                             cudaFuncAttributeMaxDynamicSharedMemorySize, ATTN_SMEM);
    }

    // s2 (high prio): kpe -> vpeA (n<512) -> vpeB (n>=512)
    // s0: proj -> (kpe) attn -> (vpeA) epiA -> (vpeB) epiB
    cudaEventRecord(ev_fork, 0);
    cudaStreamWaitEvent(s2, ev_fork, 0);
    kpe_kernel<<<NN * NN / 256, 256, 0, s2>>>(kpe);
    cudaEventRecord(ev_kpe, s2);
    vpe_kernel<<<dim3(512, 4), 256, 0, s2>>>(vpe, 0);
    cudaEventRecord(ev_vA, s2);
    vpe_kernel<<<dim3(512, 4), 256, 0, s2>>>(vpe, 512);
    cudaEventRecord(ev_vB, s2);

    proj_fused_kernel<<<BB * NN / 64, 256, FPROJ_SMEM>>>(values, Wv, Wk, Wq);
    cudaStreamWaitEvent(0, ev_kpe, 0);
    attn_kernel<<<dim3(NN / 64, BB), 256, ATTN_SMEM>>>(mask);
    cudaStreamWaitEvent(0, ev_vA, 0);
    epi_kernel<<<dim3(8, BB), 256>>>(ln_gamma, ln_beta, out, 0);
    cudaStreamWaitEvent(0, ev_vB, 0);
    epi_kernel<<<dim3(8, BB), 256>>>(ln_gamma, ln_beta, out, 512);
}

// round 12
// speedup vs baseline: 1.0216x; 1.0216x over previous
#include <cuda_runtime.h>
#include <cuda_fp16.h>

#define BB 8
#define NN 1024
#define DD 128

// ---------------- scratch (device globals; no allocation allowed) ----------
__device__ float g_v[BB * NN * DD];
__device__ float g_o[BB * NN * DD];
__device__ __half g_vh[BB * NN * DD];
__device__ __half g_kh[BB * NN * DD];
__device__ __half g_qh[BB * NN * DD];   // pre-scaled by 1/sqrt(D)
__device__ float g_kpe[NN * NN];
__device__ float g_vpe[NN * DD];

// ---------------- asm helpers ----------------------------------------------
__device__ __forceinline__ unsigned smem_u32(const void* p) {
    unsigned a;
    asm("{ .reg .u64 t; cvta.to.shared.u64 t, %1; cvt.u32.u64 %0, t; }"
        : "=r"(a) : "l"(p));
    return a;
}
__device__ __forceinline__ void ldsm_x4(unsigned& a0, unsigned& a1,
                                        unsigned& a2, unsigned& a3, unsigned addr) {
    asm volatile("ldmatrix.sync.aligned.m8n8.x4.shared.b16 {%0,%1,%2,%3}, [%4];"
                 : "=r"(a0), "=r"(a1), "=r"(a2), "=r"(a3) : "r"(addr));
}
__device__ __forceinline__ void ldsm_x2(unsigned& b0, unsigned& b1, unsigned addr) {
    asm volatile("ldmatrix.sync.aligned.m8n8.x2.shared.b16 {%0,%1}, [%2];"
                 : "=r"(b0), "=r"(b1) : "r"(addr));
}
__device__ __forceinline__ void ldsm_x2t(unsigned& b0, unsigned& b1, unsigned addr) {
    asm volatile("ldmatrix.sync.aligned.m8n8.x2.trans.shared.b16 {%0,%1}, [%2];"
                 : "=r"(b0), "=r"(b1) : "r"(addr));
}
__device__ __forceinline__ void mma_f16(float d[4], const unsigned a[4],
                                        const unsigned b[2]) {
    asm("mma.sync.aligned.m16n8k16.row.col.f32.f16.f16.f32 "
        "{%0,%1,%2,%3}, {%4,%5,%6,%7}, {%8,%9}, {%0,%1,%2,%3};"
        : "+f"(d[0]), "+f"(d[1]), "+f"(d[2]), "+f"(d[3])
        : "r"(a[0]), "r"(a[1]), "r"(a[2]), "r"(a[3]), "r"(b[0]), "r"(b[1]));
}
__device__ __forceinline__ void cp16(unsigned dst, const void* src) {
    asm volatile("cp.async.cg.shared.global [%0], [%1], 16;"
                 :: "r"(dst), "l"(src));
}
__device__ __forceinline__ float4 ldcs4(const float4* p) {
    float4 v;
    asm volatile("ld.global.cs.v4.f32 {%0,%1,%2,%3}, [%4];"
                 : "=f"(v.x), "=f"(v.y), "=f"(v.z), "=f"(v.w) : "l"(p));
    return v;
}

// ---------------- kpe[n,m] = sum_d keys_pos_enc[n,m,d] ---------------------
// round-10 version: warp-per-32-rows (4 groups of 8), coalesced 512B rows,
// MLP 8, streaming loads.
__global__ __launch_bounds__(256) void kpe_kernel(const float* __restrict__ kp) {
    int gwarp = (blockIdx.x * 256 + threadIdx.x) >> 5;
    int lane = threadIdx.x & 31;
#pragma unroll
    for (int grp = 0; grp < 4; grp++) {
        size_t row0 = (size_t)gwarp * 32 + grp * 8;
        const float4* p = reinterpret_cast<const float4*>(kp) + row0 * 32 + lane;
        float s[8];
#pragma unroll
        for (int i = 0; i < 8; i++) {
            float4 v = ldcs4(p + i * 32);
            s[i] = (v.x + v.y) + (v.z + v.w);
        }
#pragma unroll
        for (int i = 0; i < 8; i++) {
#pragma unroll
            for (int o = 16; o >= 1; o >>= 1)
                s[i] += __shfl_xor_sync(0xffffffffu, s[i], o);
        }
        float out = 0.f;
#pragma unroll
        for (int i = 0; i < 8; i++)
            if (lane == i) out = s[i];
        if (lane < 8) g_kpe[row0 + lane] = out;
    }
}

// ---------------- vpe[n,d] = sum_m values_pos_enc[n,m,d] -------------------
// round-10 version + n_base so it can run in two overlapped halves.
__global__ void vpe_kernel(const float* __restrict__ vp, int n_base) {
    __shared__ float4 red[8][32];
    int n = n_base + blockIdx.x;
    int g = threadIdx.x >> 5, lane = threadIdx.x & 31;
    const float4* base = reinterpret_cast<const float4*>(vp + (size_t)n * NN * DD);
    float4 acc[8];
#pragma unroll
    for (int i = 0; i < 8; i++) acc[i] = make_float4(0.f, 0.f, 0.f, 0.f);
    for (int m = g; m < NN; m += 64) {
#pragma unroll
        for (int i = 0; i < 8; i++) {
            float4 v = ldcs4(base + (m + i * 8) * 32 + lane);
            acc[i].x += v.x; acc[i].y += v.y; acc[i].z += v.z; acc[i].w += v.w;
        }
    }
#pragma unroll
    for (int i = 1; i < 8; i++) {
        acc[0].x += acc[i].x; acc[0].y += acc[i].y;
        acc[0].z += acc[i].z; acc[0].w += acc[i].w;
    }
    red[g][lane] = acc[0];
    __syncthreads();
    if (g == 0) {
        float4 a = red[0][lane];
#pragma unroll
        for (int i = 1; i < 8; i++) {
            float4 b = red[i][lane];
            a.x += b.x; a.y += b.y; a.z += b.z; a.w += b.w;
        }
        reinterpret_cast<float4*>(g_vpe + n * DD)[lane] = a;
    }
}

// ---------------- fused projection: v = X Wv^T; k = v Wk^T; q = v Wq^T -----
// fp32 outputs for k/q removed (dead); only g_v fp32 kept (epi residual).
#define FPROJ_SMEM ((64 * 132 + 64 * 132 + 128 * 132) * 4)

__device__ __forceinline__ void gemm_64x128(const float* __restrict__ sA,
                                            const float* __restrict__ sWt,
                                            int ty, int tx, float acc[4][8]) {
#pragma unroll
    for (int i = 0; i < 4; i++)
#pragma unroll
        for (int j = 0; j < 8; j++) acc[i][j] = 0.f;
    for (int kk = 0; kk < 128; kk += 4) {
        float4 a[4];
#pragma unroll
        for (int i = 0; i < 4; i++)
            a[i] = *reinterpret_cast<const float4*>(sA + (ty * 4 + i) * 132 + kk);
#pragma unroll
        for (int t = 0; t < 4; t++) {
            float4 b0 = *reinterpret_cast<const float4*>(sWt + (kk + t) * 132 + tx * 8);
            float4 b1 = *reinterpret_cast<const float4*>(sWt + (kk + t) * 132 + tx * 8 + 4);
#pragma unroll
            for (int i = 0; i < 4; i++) {
                float aa = reinterpret_cast<const float*>(&a[i])[t];
                acc[i][0] += aa * b0.x; acc[i][1] += aa * b0.y;
                acc[i][2] += aa * b0.z; acc[i][3] += aa * b0.w;
                acc[i][4] += aa * b1.x; acc[i][5] += aa * b1.y;
                acc[i][6] += aa * b1.z; acc[i][7] += aa * b1.w;
            }
        }
    }
}

__device__ __forceinline__ void load_wt(const float* __restrict__ W,
                                        float* __restrict__ sWt, int tid) {
    for (int it = tid; it < 128 * 32; it += 256) {
        int o = it >> 5, e4 = it & 31;
        float4 v = *reinterpret_cast<const float4*>(W + o * DD + e4 * 4);
        sWt[(e4 * 4 + 0) * 132 + o] = v.x;
        sWt[(e4 * 4 + 1) * 132 + o] = v.y;
        sWt[(e4 * 4 + 2) * 132 + o] = v.z;
        sWt[(e4 * 4 + 3) * 132 + o] = v.w;
    }
}

__device__ __forceinline__ void store_half8(__half* dst, const float* a, float sc) {
#pragma unroll
    for (int j = 0; j < 4; j++) {
        __half2 h = __floats2half2_rn(a[2 * j] * sc, a[2 * j + 1] * sc);
        *reinterpret_cast<__half2*>(dst + 2 * j) = h;
    }
}

__global__ __launch_bounds__(256) void proj_fused_kernel(
    const float* __restrict__ X, const float* __restrict__ Wv,
    const float* __restrict__ Wk, const float* __restrict__ Wq) {
    extern __shared__ float sm[];
    float* sX = sm;
    float* sV = sm + 64 * 132;
    float* sWt = sm + 2 * 64 * 132;
    const float inv_s = 0.088388347648318447f;

    int tid = threadIdx.x;
    int row0 = blockIdx.x * 64;
    int ty = tid >> 4, tx = tid & 15;
    float acc[4][8];

    for (int it = tid; it < 64 * 32; it += 256) {
        int r = it >> 5, c4 = it & 31;
        float4 v = *reinterpret_cast<const float4*>(X + (size_t)(row0 + r) * DD + c4 * 4);
        *reinterpret_cast<float4*>(sX + r * 132 + c4 * 4) = v;
    }
    load_wt(Wv, sWt, tid);
    __syncthreads();

    gemm_64x128(sX, sWt, ty, tx, acc);
    __syncthreads();
#pragma unroll
    for (int i = 0; i < 4; i++) {
        int r = ty * 4 + i;
        size_t go = (size_t)(row0 + r) * DD + tx * 8;
        float4 lo = make_float4(acc[i][0], acc[i][1], acc[i][2], acc[i][3]);
        float4 hi = make_float4(acc[i][4], acc[i][5], acc[i][6], acc[i][7]);
        *reinterpret_cast<float4*>(sV + r * 132 + tx * 8) = lo;
        *reinterpret_cast<float4*>(sV + r * 132 + tx * 8 + 4) = hi;
        *reinterpret_cast<float4*>(g_v + go) = lo;
        *reinterpret_cast<float4*>(g_v + go + 4) = hi;
        store_half8(g_vh + go, acc[i], 1.0f);
    }
    load_wt(Wk, sWt, tid);
    __syncthreads();

    gemm_64x128(sV, sWt, ty, tx, acc);
#pragma unroll
    for (int i = 0; i < 4; i++) {
        size_t go = (size_t)(row0 + ty * 4 + i) * DD + tx * 8;
        store_half8(g_kh + go, acc[i], 1.0f);
    }
    __syncthreads();
    load_wt(Wq, sWt, tid);
    __syncthreads();

    gemm_64x128(sV, sWt, ty, tx, acc);
#pragma unroll
    for (int i = 0; i < 4; i++) {
        size_t go = (size_t)(row0 + ty * 4 + i) * DD + tx * 8;
        store_half8(g_qh + go, acc[i], inv_s);   // pre-scaled q
    }
}

// ---------------- fp16 tensor-core flash attention (round-7, known-good) ----
#define HQS 136
#define HKS 136
#define HVS 136
#define HPS 72
#define ATTN_SMEM ((64*HQS + 2*64*HKS + 2*64*HVS + 64*HPS) * 2 + 512 * 4)

__global__ __launch_bounds__(256) void attn_kernel(const int* __restrict__ mask) {
    extern __shared__ __half hsm[];
    __half* sQ = hsm;                         // 64 x 136
    __half* sK = sQ + 64 * HQS;               // 2 x 64 x 136
    __half* sV = sK + 2 * 64 * HKS;           // 2 x 64 x 136
    __half* sP = sV + 2 * 64 * HVS;           // 64 x 72
    float* sM = reinterpret_cast<float*>(sP + 64 * HPS);  // 2 x 64
    float* sL = sM + 128;                     // 2 x 64
    float* sRMax = sL + 128;                  // 64 x 2
    float* sRSum = sRMax + 128;               // 64 x 2

    int tid = threadIdx.x;
    int b = blockIdx.y;
    int n0 = blockIdx.x * 64;
    int w = tid >> 5, lane = tid & 31;
    int mi = w & 3, ni = w >> 2;
    int qg = lane >> 2, qt = lane & 3;
    const float inv_s = 0.088388347648318447f;

    unsigned uQ = smem_u32(sQ);
    unsigned uK = smem_u32(sK);
    unsigned uV = smem_u32(sV);
    unsigned uP = smem_u32(sP);
    int l15 = lane & 15, l7 = lane & 7;

    // ---- load Q tile (fp16, already pre-scaled) ----
    for (int it = tid; it < 64 * 16; it += 256) {
        int r = it >> 4, c8 = it & 15;
        uint4 v = *reinterpret_cast<const uint4*>(
            g_qh + ((size_t)(b * NN + n0 + r)) * DD + c8 * 8);
        *reinterpret_cast<uint4*>(sQ + r * HQS + c8 * 8) = v;
    }
    if (tid < 64) { sM[tid] = -1e30f; sL[tid] = 0.f; }

    // ---- prologue: cp.async tile 0 into buffer 0 ----
    {
        const __half* kb = g_kh + ((size_t)(b * NN)) * DD;
        const __half* vb = g_vh + ((size_t)(b * NN)) * DD;
        for (int it = tid; it < 1024; it += 256) {
            int r = it >> 4, c16 = it & 15;
            cp16(uK + (r * HKS + c16 * 8) * 2, kb + r * DD + c16 * 8);
            cp16(uV + (r * HVS + c16 * 8) * 2, vb + r * DD + c16 * 8);
        }
        asm volatile("cp.async.commit_group;");
    }

    int lr0 = mi * 16 + qg, lr1 = lr0 + 8;

    float acc_o[8][4];
#pragma unroll
    for (int i = 0; i < 8; i++)
#pragma unroll
        for (int j = 0; j < 4; j++) acc_o[i][j] = 0.f;

    for (int t = 0; t < 16; t++) {
        int p = t & 1;
        int m0 = t * 64;
        unsigned uKb = uK + p * (64 * HKS * 2);
        unsigned uVb = uV + p * (64 * HVS * 2);

        // prefetch tile t+1 into other buffer, then wait for tile t
        if (t < 15) {
            int q2 = 1 - p;
            const __half* kb = g_kh + ((size_t)(b * NN + m0 + 64)) * DD;
            const __half* vb = g_vh + ((size_t)(b * NN + m0 + 64)) * DD;
            unsigned dK = uK + q2 * (64 * HKS * 2);
            unsigned dV = uV + q2 * (64 * HVS * 2);
            for (int it = tid; it < 1024; it += 256) {
                int r = it >> 4, c16 = it & 15;
                cp16(dK + (r * HKS + c16 * 8) * 2, kb + r * DD + c16 * 8);
                cp16(dV + (r * HVS + c16 * 8) * 2, vb + r * DD + c16 * 8);
            }
            asm volatile("cp.async.commit_group;");
            asm volatile("cp.async.wait_group 1;");
        } else {
            asm volatile("cp.async.wait_group 0;");
        }
        __syncthreads();   // tile t K/V visible; prior tile's sP/sM/sL reads done

        // ---- prefetch kpe/mask rows (overlaps S mma) ----
        const float* kp0 = g_kpe + (size_t)(n0 + lr0) * NN + m0 + ni * 32;
        const float* kp1 = g_kpe + (size_t)(n0 + lr1) * NN + m0 + ni * 32;
        const int* mr0 = mask + ((size_t)b * NN + n0 + lr0) * NN + m0 + ni * 32;
        const int* mr1 = mask + ((size_t)b * NN + n0 + lr1) * NN + m0 + ni * 32;
        float2 kv0[4], kv1[4];
        int2 mv0[4], mv1[4];
#pragma unroll
        for (int nt = 0; nt < 4; nt++) {
            int c = nt * 8 + 2 * qt;
            kv0[nt] = *reinterpret_cast<const float2*>(kp0 + c);
            kv1[nt] = *reinterpret_cast<const float2*>(kp1 + c);
            mv0[nt] = *reinterpret_cast<const int2*>(mr0 + c);
            mv1[nt] = *reinterpret_cast<const int2*>(mr1 + c);
        }

        // ---- S = Q K^T : warp tile 16x32, fp16 m16n8k16 ----
        float acc_s[4][4];
#pragma unroll
        for (int i = 0; i < 4; i++)
#pragma unroll
            for (int j = 0; j < 4; j++) acc_s[i][j] = 0.f;
#pragma unroll
        for (int ks = 0; ks < 8; ks++) {
            unsigned a[4];
            ldsm_x4(a[0], a[1], a[2], a[3],
                    uQ + ((mi * 16 + l15) * HQS + ks * 16 + (lane >> 4) * 8) * 2);
#pragma unroll
            for (int nt = 0; nt < 4; nt++) {
                unsigned bf[2];
                ldsm_x2(bf[0], bf[1],
                        uKb + ((ni * 32 + nt * 8 + l7) * HKS + ks * 16 +
                               ((lane >> 3) & 1) * 8) * 2);
                mma_f16(acc_s[nt], a, bf);
            }
        }

        // ---- + kpe/sqrt(D), mask; segment max ----
        float lmax0 = -1e30f, lmax1 = -1e30f;
#pragma unroll
        for (int nt = 0; nt < 4; nt++) {
            float e00 = acc_s[nt][0] + kv0[nt].x * inv_s; if (mv0[nt].x == 0) e00 = -1e30f;
            float e01 = acc_s[nt][1] + kv0[nt].y * inv_s; if (mv0[nt].y == 0) e01 = -1e30f;
            acc_s[nt][0] = e00; acc_s[nt][1] = e01;
            lmax0 = fmaxf(lmax0, fmaxf(e00, e01));
            float e10 = acc_s[nt][2] + kv1[nt].x * inv_s; if (mv1[nt].x == 0) e10 = -1e30f;
            float e11 = acc_s[nt][3] + kv1[nt].y * inv_s; if (mv1[nt].y == 0) e11 = -1e30f;
            acc_s[nt][2] = e10; acc_s[nt][3] = e11;
            lmax1 = fmaxf(lmax1, fmaxf(e10, e11));
        }
        lmax0 = fmaxf(lmax0, __shfl_xor_sync(0xffffffffu, lmax0, 1));
        lmax0 = fmaxf(lmax0, __shfl_xor_sync(0xffffffffu, lmax0, 2));
        lmax1 = fmaxf(lmax1, __shfl_xor_sync(0xffffffffu, lmax1, 1));
        lmax1 = fmaxf(lmax1, __shfl_xor_sync(0xffffffffu, lmax1, 2));
        if (qt == 0) {
            sRMax[lr0 * 2 + ni] = lmax0;
            sRMax[lr1 * 2 + ni] = lmax1;
        }
        __syncthreads();

        // ---- online softmax; write P (fp16) ----
        float mo0 = sM[p * 64 + lr0], mo1 = sM[p * 64 + lr1];
        float mn0 = fmaxf(mo0, fmaxf(sRMax[lr0 * 2], sRMax[lr0 * 2 + 1]));
        float mn1 = fmaxf(mo1, fmaxf(sRMax[lr1 * 2], sRMax[lr1 * 2 + 1]));
        float f0 = __expf(mo0 - mn0), f1 = __expf(mo1 - mn1);
        float ls0 = 0.f, ls1 = 0.f;
#pragma unroll
        for (int nt = 0; nt < 4; nt++) {
            int c = ni * 32 + nt * 8 + 2 * qt;
            float p00 = (acc_s[nt][0] < -5e29f) ? 0.f : __expf(acc_s[nt][0] - mn0);
            float p01 = (acc_s[nt][1] < -5e29f) ? 0.f : __expf(acc_s[nt][1] - mn0);
            *reinterpret_cast<__half2*>(sP + lr0 * HPS + c) = __floats2half2_rn(p00, p01);
            ls0 += p00 + p01;
            float p10 = (acc_s[nt][2] < -5e29f) ? 0.f : __expf(acc_s[nt][2] - mn1);
            float p11 = (acc_s[nt][3] < -5e29f) ? 0.f : __expf(acc_s[nt][3] - mn1);
            *reinterpret_cast<__half2*>(sP + lr1 * HPS + c) = __floats2half2_rn(p10, p11);
            ls1 += p10 + p11;
        }
        ls0 += __shfl_xor_sync(0xffffffffu, ls0, 1);
        ls0 += __shfl_xor_sync(0xffffffffu, ls0, 2);
        ls1 += __shfl_xor_sync(0xffffffffu, ls1, 1);
        ls1 += __shfl_xor_sync(0xffffffffu, ls1, 2);
        if (qt == 0) {
            sRSum[lr0 * 2 + ni] = ls0;
            sRSum[lr1 * 2 + ni] = ls1;
        }
        // rescale O accumulators
#pragma unroll
        for (int nt = 0; nt < 8; nt++) {
            acc_o[nt][0] *= f0; acc_o[nt][1] *= f0;
            acc_o[nt][2] *= f1; acc_o[nt][3] *= f1;
        }
        __syncthreads();  // sP + sRSum complete

        if (ni == 0 && qt == 0) {
            int q2 = 1 - p;
            sM[q2 * 64 + lr0] = mn0;
            sL[q2 * 64 + lr0] = sL[p * 64 + lr0] * f0 + sRSum[lr0 * 2] + sRSum[lr0 * 2 + 1];
            sM[q2 * 64 + lr1] = mn1;
            sL[q2 * 64 + lr1] = sL[p * 64 + lr1] * f1 + sRSum[lr1 * 2] + sRSum[lr1 * 2 + 1];
        }

        // ---- O += P V : warp tile 16x64, fp16 m16n8k16, V via ldmatrix.trans ----
#pragma unroll
        for (int ks = 0; ks < 4; ks++) {
            unsigned a[4];
            ldsm_x4(a[0], a[1], a[2], a[3],
                    uP + ((mi * 16 + l15) * HPS + ks * 16 + (lane >> 4) * 8) * 2);
#pragma unroll
            for (int nt = 0; nt < 8; nt++) {
                unsigned bf[2];
                ldsm_x2t(bf[0], bf[1],
                         uVb + ((ks * 16 + l15) * HVS + ni * 64 + nt * 8) * 2);
                mma_f16(acc_o[nt], a, bf);
            }
        }
    }

    __syncthreads();  // final sM/sL (parity 0 after t=15) visible
    float il0 = 1.0f / sL[lr0];
    float il1 = 1.0f / sL[lr1];
    float* o0 = g_o + ((size_t)(b * NN + n0 + lr0)) * DD;
    float* o1 = g_o + ((size_t)(b * NN + n0 + lr1)) * DD;
#pragma unroll
    for (int nt = 0; nt < 8; nt++) {
        int c = ni * 64 + nt * 8 + 2 * qt;
        *reinterpret_cast<float2*>(o0 + c) =
            make_float2(acc_o[nt][0] * il0, acc_o[nt][1] * il0);
        *reinterpret_cast<float2*>(o1 + c) =
            make_float2(acc_o[nt][2] * il1, acc_o[nt][3] * il1);
    }
}

// ---------------- epilogue: out = LN(O + vpe) + v ---------------------------
__global__ __launch_bounds__(256) void epi_kernel(
    const float* __restrict__ gamma, const float* __restrict__ beta,
    float* __restrict__ out, int n_off) {
    int tid = threadIdx.x;
    int b = blockIdx.y;
    int n = n_off + blockIdx.x * 64 + (tid >> 2);
    int part = tid & 3;

    const float* orow = g_o + ((size_t)(b * NN + n)) * DD;
    const float* vper = g_vpe + n * DD;
    float x[32];
    float sum = 0.f, sq = 0.f;
#pragma unroll
    for (int u = 0; u < 32; u += 4) {
        int d = part * 32 + u;
        float4 o4 = *reinterpret_cast<const float4*>(orow + d);
        float4 p4 = *reinterpret_cast<const float4*>(vper + d);
        float4 v;
        v.x = o4.x + p4.x; v.y = o4.y + p4.y;
        v.z = o4.z + p4.z; v.w = o4.w + p4.w;
        x[u] = v.x; x[u + 1] = v.y; x[u + 2] = v.z; x[u + 3] = v.w;
        sum += v.x + v.y + v.z + v.w;
        sq += v.x * v.x + v.y * v.y + v.z * v.z + v.w * v.w;
    }
#pragma unroll
    for (int o = 1; o <= 2; o <<= 1) {
        sum += __shfl_xor_sync(0xffffffffu, sum, o);
        sq += __shfl_xor_sync(0xffffffffu, sq, o);
    }
    float mu = sum * (1.f / 128.f);
    float var = sq * (1.f / 128.f) - mu * mu;
    float rstd = rsqrtf(var + 1e-5f);
    const float* gvr = g_v + ((size_t)(b * NN + n)) * DD;
    float* orow_out = out + ((size_t)(b * NN + n)) * DD;
#pragma unroll
    for (int u = 0; u < 32; u += 4) {
        int d = part * 32 + u;
        float4 gm = *reinterpret_cast<const float4*>(gamma + d);
        float4 bt = *reinterpret_cast<const float4*>(beta + d);
        float4 vv = *reinterpret_cast<const float4*>(gvr + d);
        float4 r4;
        r4.x = (x[u] - mu) * rstd * gm.x + bt.x + vv.x;
        r4.y = (x[u + 1] - mu) * rstd * gm.y + bt.y + vv.y;
        r4.z = (x[u + 2] - mu) * rstd * gm.z + bt.z + vv.z;
        r4.w = (x[u + 3] - mu) * rstd * gm.w + bt.w + vv.w;
        *reinterpret_cast<float4*>(orow_out + d) = r4;
    }
}

// ---------------- launch ---------------------------------------------------
extern "C" void kernel_launch(void* const* d_in, const int* in_sizes, int n_in,
                              void* d_out, int out_size) {
    const float* values = (const float*)d_in[0];
    const int* mask = (const int*)d_in[3];
    const float* vpe = (const float*)d_in[4];
    const float* kpe = (const float*)d_in[5];
    const float* Wv = (const float*)d_in[6];
    const float* Wk = (const float*)d_in[7];
    const float* Wq = (const float*)d_in[8];
    const float* ln_gamma = (const float*)d_in[9];
    const float* ln_beta = (const float*)d_in[10];
    float* out = (float*)d_out;

    static cudaStream_t s2 = nullptr;
    static cudaEvent_t ev_fork = nullptr, ev_kpe = nullptr,
                       ev_vA = nullptr, ev_vB = nullptr;
    if (!s2) {
        cudaStreamCreateWithFlags(&s2, cudaStreamNonBlocking);   // default priority
        cudaEventCreateWithFlags(&ev_fork, cudaEventDisableTiming);
        cudaEventCreateWithFlags(&ev_kpe, cudaEventDisableTiming);
        cudaEventCreateWithFlags(&ev_vA, cudaEventDisableTiming);
        cudaEventCreateWithFlags(&ev_vB, cudaEventDisableTiming);
        cudaFuncSetAttribute(proj_fused_kernel,
                             cudaFuncAttributeMaxDynamicSharedMemorySize, FPROJ_SMEM);
        cudaFuncSetAttribute(attn_kernel,
                             cudaFuncAttributeMaxDynamicSharedMemorySize, ATTN_SMEM);
    }

    // s2: kpe -> vpeA (n<512) -> vpeB (n>=512)
    // s0: proj -> (kpe) attn -> (vpeA) epiA -> (vpeB) epiB
    cudaEventRecord(ev_fork, 0);
    cudaStreamWaitEvent(s2, ev_fork, 0);
    kpe_kernel<<<NN * NN / 256, 256, 0, s2>>>(kpe);   // round-10 kpe, 4096 blocks
    cudaEventRecord(ev_kpe, s2);
    vpe_kernel<<<512, 256, 0, s2>>>(vpe, 0);
    cudaEventRecord(ev_vA, s2);
    vpe_kernel<<<512, 256, 0, s2>>>(vpe, 512);
    cudaEventRecord(ev_vB, s2);

    proj_fused_kernel<<<BB * NN / 64, 256, FPROJ_SMEM>>>(values, Wv, Wk, Wq);
    cudaStreamWaitEvent(0, ev_kpe, 0);
    attn_kernel<<<dim3(NN / 64, BB), 256, ATTN_SMEM>>>(mask);
    cudaStreamWaitEvent(0, ev_vA, 0);
    epi_kernel<<<dim3(8, BB), 256>>>(ln_gamma, ln_beta, out, 0);
    cudaStreamWaitEvent(0, ev_vB, 0);
    epi_kernel<<<dim3(8, BB), 256>>>(ln_gamma, ln_beta, out, 512);
}

// round 14
// speedup vs baseline: 1.1140x; 1.0904x over previous
#include <cuda_runtime.h>
#include <cuda_fp16.h>

#define BB 8
#define NN 1024
#define DD 128

// ---------------- scratch (device globals; no allocation allowed) ----------
__device__ float g_v[BB * NN * DD];
__device__ float g_o[BB * NN * DD];
__device__ __half g_vh[BB * NN * DD];
__device__ __half g_kh[BB * NN * DD];
__device__ __half g_qh[BB * NN * DD];   // pre-scaled by 1/sqrt(D)
__device__ float g_kpe[NN * NN];
__device__ float g_vpe[NN * DD];

// ---------------- asm helpers ----------------------------------------------
__device__ __forceinline__ unsigned smem_u32(const void* p) {
    unsigned a;
    asm("{ .reg .u64 t; cvta.to.shared.u64 t, %1; cvt.u32.u64 %0, t; }"
        : "=r"(a) : "l"(p));
    return a;
}
__device__ __forceinline__ void ldsm_x4(unsigned& a0, unsigned& a1,
                                        unsigned& a2, unsigned& a3, unsigned addr) {
    asm volatile("ldmatrix.sync.aligned.m8n8.x4.shared.b16 {%0,%1,%2,%3}, [%4];"
                 : "=r"(a0), "=r"(a1), "=r"(a2), "=r"(a3) : "r"(addr));
}
__device__ __forceinline__ void ldsm_x2(unsigned& b0, unsigned& b1, unsigned addr) {
    asm volatile("ldmatrix.sync.aligned.m8n8.x2.shared.b16 {%0,%1}, [%2];"
                 : "=r"(b0), "=r"(b1) : "r"(addr));
}
__device__ __forceinline__ void ldsm_x2t(unsigned& b0, unsigned& b1, unsigned addr) {
    asm volatile("ldmatrix.sync.aligned.m8n8.x2.trans.shared.b16 {%0,%1}, [%2];"
                 : "=r"(b0), "=r"(b1) : "r"(addr));
}
__device__ __forceinline__ void mma_f16(float d[4], const unsigned a[4],
                                        const unsigned b[2]) {
    asm("mma.sync.aligned.m16n8k16.row.col.f32.f16.f16.f32 "
        "{%0,%1,%2,%3}, {%4,%5,%6,%7}, {%8,%9}, {%0,%1,%2,%3};"
        : "+f"(d[0]), "+f"(d[1]), "+f"(d[2]), "+f"(d[3])
        : "r"(a[0]), "r"(a[1]), "r"(a[2]), "r"(a[3]), "r"(b[0]), "r"(b[1]));
}
__device__ __forceinline__ void cp16(unsigned dst, const void* src) {
    asm volatile("cp.async.cg.shared.global [%0], [%1], 16;"
                 :: "r"(dst), "l"(src));
}
__device__ __forceinline__ float4 ldcs4(const float4* p) {
    float4 v;
    asm volatile("ld.global.cs.v4.f32 {%0,%1,%2,%3}, [%4];"
                 : "=f"(v.x), "=f"(v.y), "=f"(v.z), "=f"(v.w) : "l"(p));
    return v;
}

// ---------------- kpe[n,m] = sum_d keys_pos_enc[n,m,d] ---------------------
// warp-per-32-rows (4 groups of 8), coalesced 512B rows, MLP 8, streaming.
__global__ __launch_bounds__(256) void kpe_kernel(const float* __restrict__ kp) {
    int gwarp = (blockIdx.x * 256 + threadIdx.x) >> 5;
    int lane = threadIdx.x & 31;
#pragma unroll
    for (int grp = 0; grp < 4; grp++) {
        size_t row0 = (size_t)gwarp * 32 + grp * 8;
        const float4* p = reinterpret_cast<const float4*>(kp) + row0 * 32 + lane;
        float s[8];
#pragma unroll
        for (int i = 0; i < 8; i++) {
            float4 v = ldcs4(p + i * 32);
            s[i] = (v.x + v.y) + (v.z + v.w);
        }
#pragma unroll
        for (int i = 0; i < 8; i++) {
#pragma unroll
            for (int o = 16; o >= 1; o >>= 1)
                s[i] += __shfl_xor_sync(0xffffffffu, s[i], o);
        }
        float out = 0.f;
#pragma unroll
        for (int i = 0; i < 8; i++)
            if (lane == i) out = s[i];
        if (lane < 8) g_kpe[row0 + lane] = out;
    }
}

// ---------------- vpe[n,d] = sum_m values_pos_enc[n,m,d] -------------------
// single launch (1024 CTAs), 8 independent acc chains, streaming loads.
__global__ void vpe_kernel(const float* __restrict__ vp) {
    __shared__ float4 red[8][32];
    int n = blockIdx.x;
    int g = threadIdx.x >> 5, lane = threadIdx.x & 31;
    const float4* base = reinterpret_cast<const float4*>(vp + (size_t)n * NN * DD);
    float4 acc[8];
#pragma unroll
    for (int i = 0; i < 8; i++) acc[i] = make_float4(0.f, 0.f, 0.f, 0.f);
    for (int m = g; m < NN; m += 64) {
#pragma unroll
        for (int i = 0; i < 8; i++) {
            float4 v = ldcs4(base + (m + i * 8) * 32 + lane);
            acc[i].x += v.x; acc[i].y += v.y; acc[i].z += v.z; acc[i].w += v.w;
        }
    }
#pragma unroll
    for (int i = 1; i < 8; i++) {
        acc[0].x += acc[i].x; acc[0].y += acc[i].y;
        acc[0].z += acc[i].z; acc[0].w += acc[i].w;
    }
    red[g][lane] = acc[0];
    __syncthreads();
    if (g == 0) {
        float4 a = red[0][lane];
#pragma unroll
        for (int i = 1; i < 8; i++) {
            float4 b = red[i][lane];
            a.x += b.x; a.y += b.y; a.z += b.z; a.w += b.w;
        }
        reinterpret_cast<float4*>(g_vpe + n * DD)[lane] = a;
    }
}

// ---------------- fused projection: v = X Wv^T; k = v Wk^T; q = v Wq^T -----
#define FPROJ_SMEM ((64 * 132 + 64 * 132 + 128 * 132) * 4)

__device__ __forceinline__ void gemm_64x128(const float* __restrict__ sA,
                                            const float* __restrict__ sWt,
                                            int ty, int tx, float acc[4][8]) {
#pragma unroll
    for (int i = 0; i < 4; i++)
#pragma unroll
        for (int j = 0; j < 8; j++) acc[i][j] = 0.f;
    for (int kk = 0; kk < 128; kk += 4) {
        float4 a[4];
#pragma unroll
        for (int i = 0; i < 4; i++)
            a[i] = *reinterpret_cast<const float4*>(sA + (ty * 4 + i) * 132 + kk);
#pragma unroll
        for (int t = 0; t < 4; t++) {
            float4 b0 = *reinterpret_cast<const float4*>(sWt + (kk + t) * 132 + tx * 8);
            float4 b1 = *reinterpret_cast<const float4*>(sWt + (kk + t) * 132 + tx * 8 + 4);
#pragma unroll
            for (int i = 0; i < 4; i++) {
                float aa = reinterpret_cast<const float*>(&a[i])[t];
                acc[i][0] += aa * b0.x; acc[i][1] += aa * b0.y;
                acc[i][2] += aa * b0.z; acc[i][3] += aa * b0.w;
                acc[i][4] += aa * b1.x; acc[i][5] += aa * b1.y;
                acc[i][6] += aa * b1.z; acc[i][7] += aa * b1.w;
            }
        }
    }
}

__device__ __forceinline__ void load_wt(const float* __restrict__ W,
                                        float* __restrict__ sWt, int tid) {
    for (int it = tid; it < 128 * 32; it += 256) {
        int o = it >> 5, e4 = it & 31;
        float4 v = *reinterpret_cast<const float4*>(W + o * DD + e4 * 4);
        sWt[(e4 * 4 + 0) * 132 + o] = v.x;
        sWt[(e4 * 4 + 1) * 132 + o] = v.y;
        sWt[(e4 * 4 + 2) * 132 + o] = v.z;
        sWt[(e4 * 4 + 3) * 132 + o] = v.w;
    }
}

__device__ __forceinline__ void store_half8(__half* dst, const float* a, float sc) {
#pragma unroll
    for (int j = 0; j < 4; j++) {
        __half2 h = __floats2half2_rn(a[2 * j] * sc, a[2 * j + 1] * sc);
        *reinterpret_cast<__half2*>(dst + 2 * j) = h;
    }
}

__global__ __launch_bounds__(256) void proj_fused_kernel(
    const float* __restrict__ X, const float* __restrict__ Wv,
    const float* __restrict__ Wk, const float* __restrict__ Wq) {
    extern __shared__ float sm[];
    float* sX = sm;
    float* sV = sm + 64 * 132;
    float* sWt = sm + 2 * 64 * 132;
    const float inv_s = 0.088388347648318447f;

    int tid = threadIdx.x;
    int row0 = blockIdx.x * 64;
    int ty = tid >> 4, tx = tid & 15;
    float acc[4][8];

    for (int it = tid; it < 64 * 32; it += 256) {
        int r = it >> 5, c4 = it & 31;
        float4 v = *reinterpret_cast<const float4*>(X + (size_t)(row0 + r) * DD + c4 * 4);
        *reinterpret_cast<float4*>(sX + r * 132 + c4 * 4) = v;
    }
    load_wt(Wv, sWt, tid);
    __syncthreads();

    gemm_64x128(sX, sWt, ty, tx, acc);
    __syncthreads();
#pragma unroll
    for (int i = 0; i < 4; i++) {
        int r = ty * 4 + i;
        size_t go = (size_t)(row0 + r) * DD + tx * 8;
        float4 lo = make_float4(acc[i][0], acc[i][1], acc[i][2], acc[i][3]);
        float4 hi = make_float4(acc[i][4], acc[i][5], acc[i][6], acc[i][7]);
        *reinterpret_cast<float4*>(sV + r * 132 + tx * 8) = lo;
        *reinterpret_cast<float4*>(sV + r * 132 + tx * 8 + 4) = hi;
        *reinterpret_cast<float4*>(g_v + go) = lo;
        *reinterpret_cast<float4*>(g_v + go + 4) = hi;
        store_half8(g_vh + go, acc[i], 1.0f);
    }
    load_wt(Wk, sWt, tid);
    __syncthreads();

    gemm_64x128(sV, sWt, ty, tx, acc);
#pragma unroll
    for (int i = 0; i < 4; i++) {
        size_t go = (size_t)(row0 + ty * 4 + i) * DD + tx * 8;
        store_half8(g_kh + go, acc[i], 1.0f);
    }
    __syncthreads();
    load_wt(Wq, sWt, tid);
    __syncthreads();

    gemm_64x128(sV, sWt, ty, tx, acc);
#pragma unroll
    for (int i = 0; i < 4; i++) {
        size_t go = (size_t)(row0 + ty * 4 + i) * DD + tx * 8;
        store_half8(g_qh + go, acc[i], inv_s);   // pre-scaled q
    }
}

// ---------------- fp16 tensor-core flash attention ---------------------------
// RACE FIX vs rounds 7-13: a __syncthreads() at the top of the tile loop,
// BEFORE issuing cp.async into buffer q2 — that buffer is the one read by the
// previous iteration's PV mma; without the barrier a fast warp could overwrite
// it while a slow warp was still reading (source of the post-timing divergence).
#define HQS 136
#define HKS 136
#define HVS 136
#define HPS 72
#define ATTN_SMEM ((64*HQS + 2*64*HKS + 2*64*HVS + 64*HPS) * 2 + 512 * 4)

__global__ __launch_bounds__(256) void attn_kernel(const int* __restrict__ mask) {
    extern __shared__ __half hsm[];
    __half* sQ = hsm;                         // 64 x 136
    __half* sK = sQ + 64 * HQS;               // 2 x 64 x 136
    __half* sV = sK + 2 * 64 * HKS;           // 2 x 64 x 136
    __half* sP = sV + 2 * 64 * HVS;           // 64 x 72
    float* sM = reinterpret_cast<float*>(sP + 64 * HPS);  // 2 x 64
    float* sL = sM + 128;                     // 2 x 64
    float* sRMax = sL + 128;                  // 64 x 2
    float* sRSum = sRMax + 128;               // 64 x 2

    int tid = threadIdx.x;
    int b = blockIdx.y;
    int n0 = blockIdx.x * 64;
    int w = tid >> 5, lane = tid & 31;
    int mi = w & 3, ni = w >> 2;
    int qg = lane >> 2, qt = lane & 3;
    const float inv_s = 0.088388347648318447f;

    unsigned uQ = smem_u32(sQ);
    unsigned uK = smem_u32(sK);
    unsigned uV = smem_u32(sV);
    unsigned uP = smem_u32(sP);
    int l15 = lane & 15, l7 = lane & 7;

    // ---- load Q tile (fp16, already pre-scaled) ----
    for (int it = tid; it < 64 * 16; it += 256) {
        int r = it >> 4, c8 = it & 15;
        uint4 v = *reinterpret_cast<const uint4*>(
            g_qh + ((size_t)(b * NN + n0 + r)) * DD + c8 * 8);
        *reinterpret_cast<uint4*>(sQ + r * HQS + c8 * 8) = v;
    }
    if (tid < 64) { sM[tid] = -1e30f; sL[tid] = 0.f; }

    // ---- prologue: cp.async tile 0 into buffer 0 ----
    {
        const __half* kb = g_kh + ((size_t)(b * NN)) * DD;
        const __half* vb = g_vh + ((size_t)(b * NN)) * DD;
        for (int it = tid; it < 1024; it += 256) {
            int r = it >> 4, c16 = it & 15;
            cp16(uK + (r * HKS + c16 * 8) * 2, kb + r * DD + c16 * 8);
            cp16(uV + (r * HVS + c16 * 8) * 2, vb + r * DD + c16 * 8);
        }
        asm volatile("cp.async.commit_group;");
    }

    int lr0 = mi * 16 + qg, lr1 = lr0 + 8;

    float acc_o[8][4];
#pragma unroll
    for (int i = 0; i < 8; i++)
#pragma unroll
        for (int j = 0; j < 4; j++) acc_o[i][j] = 0.f;

    for (int t = 0; t < 16; t++) {
        int p = t & 1;
        int m0 = t * 64;
        unsigned uKb = uK + p * (64 * HKS * 2);
        unsigned uVb = uV + p * (64 * HVS * 2);

        // RACE FIX: all warps must be done with the previous iteration's reads
        // of buffer q2 before any warp overwrites it via cp.async.
        __syncthreads();

        // prefetch tile t+1 into other buffer, then wait for tile t
        if (t < 15) {
            int q2 = 1 - p;
            const __half* kb = g_kh + ((size_t)(b * NN + m0 + 64)) * DD;
            const __half* vb = g_vh + ((size_t)(b * NN + m0 + 64)) * DD;
            unsigned dK = uK + q2 * (64 * HKS * 2);
            unsigned dV = uV + q2 * (64 * HVS * 2);
            for (int it = tid; it < 1024; it += 256) {
                int r = it >> 4, c16 = it & 15;
                cp16(dK + (r * HKS + c16 * 8) * 2, kb + r * DD + c16 * 8);
                cp16(dV + (r * HVS + c16 * 8) * 2, vb + r * DD + c16 * 8);
            }
            asm volatile("cp.async.commit_group;");
            asm volatile("cp.async.wait_group 1;");
        } else {
            asm volatile("cp.async.wait_group 0;");
        }
        __syncthreads();   // tile t K/V visible to all warps

        // ---- prefetch kpe/mask rows (overlaps S mma) ----
        const float* kp0 = g_kpe + (size_t)(n0 + lr0) * NN + m0 + ni * 32;
        const float* kp1 = g_kpe + (size_t)(n0 + lr1) * NN + m0 + ni * 32;
        const int* mr0 = mask + ((size_t)b * NN + n0 + lr0) * NN + m0 + ni * 32;
        const int* mr1 = mask + ((size_t)b * NN + n0 + lr1) * NN + m0 + ni * 32;
        float2 kv0[4], kv1[4];
        int2 mv0[4], mv1[4];
#pragma unroll
        for (int nt = 0; nt < 4; nt++) {
            int c = nt * 8 + 2 * qt;
            kv0[nt] = *reinterpret_cast<const float2*>(kp0 + c);
            kv1[nt] = *reinterpret_cast<const float2*>(kp1 + c);
            mv0[nt] = *reinterpret_cast<const int2*>(mr0 + c);
            mv1[nt] = *reinterpret_cast<const int2*>(mr1 + c);
        }

        // ---- S = Q K^T : warp tile 16x32, fp16 m16n8k16 ----
        float acc_s[4][4];
#pragma unroll
        for (int i = 0; i < 4; i++)
#pragma unroll
            for (int j = 0; j < 4; j++) acc_s[i][j] = 0.f;
#pragma unroll
        for (int ks = 0; ks < 8; ks++) {
            unsigned a[4];
            ldsm_x4(a[0], a[1], a[2], a[3],
                    uQ + ((mi * 16 + l15) * HQS + ks * 16 + (lane >> 4) * 8) * 2);
#pragma unroll
            for (int nt = 0; nt < 4; nt++) {
                unsigned bf[2];
                ldsm_x2(bf[0], bf[1],
                        uKb + ((ni * 32 + nt * 8 + l7) * HKS + ks * 16 +
                               ((lane >> 3) & 1) * 8) * 2);
                mma_f16(acc_s[nt], a, bf);
            }
        }

        // ---- + kpe/sqrt(D), mask; segment max ----
        float lmax0 = -1e30f, lmax1 = -1e30f;
#pragma unroll
        for (int nt = 0; nt < 4; nt++) {
            float e00 = acc_s[nt][0] + kv0[nt].x * inv_s; if (mv0[nt].x == 0) e00 = -1e30f;
            float e01 = acc_s[nt][1] + kv0[nt].y * inv_s; if (mv0[nt].y == 0) e01 = -1e30f;
            acc_s[nt][0] = e00; acc_s[nt][1] = e01;
            lmax0 = fmaxf(lmax0, fmaxf(e00, e01));
            float e10 = acc_s[nt][2] + kv1[nt].x * inv_s; if (mv1[nt].x == 0) e10 = -1e30f;
            float e11 = acc_s[nt][3] + kv1[nt].y * inv_s; if (mv1[nt].y == 0) e11 = -1e30f;
            acc_s[nt][2] = e10; acc_s[nt][3] = e11;
            lmax1 = fmaxf(lmax1, fmaxf(e10, e11));
        }
        lmax0 = fmaxf(lmax0, __shfl_xor_sync(0xffffffffu, lmax0, 1));
        lmax0 = fmaxf(lmax0, __shfl_xor_sync(0xffffffffu, lmax0, 2));
        lmax1 = fmaxf(lmax1, __shfl_xor_sync(0xffffffffu, lmax1, 1));
        lmax1 = fmaxf(lmax1, __shfl_xor_sync(0xffffffffu, lmax1, 2));
        if (qt == 0) {
            sRMax[lr0 * 2 + ni] = lmax0;
            sRMax[lr1 * 2 + ni] = lmax1;
        }
        __syncthreads();

        // ---- online softmax; write P (fp16) ----
        float mo0 = sM[p * 64 + lr0], mo1 = sM[p * 64 + lr1];
        float mn0 = fmaxf(mo0, fmaxf(sRMax[lr0 * 2], sRMax[lr0 * 2 + 1]));
        float mn1 = fmaxf(mo1, fmaxf(sRMax[lr1 * 2], sRMax[lr1 * 2 + 1]));
        float f0 = __expf(mo0 - mn0), f1 = __expf(mo1 - mn1);
        float ls0 = 0.f, ls1 = 0.f;
#pragma unroll
        for (int nt = 0; nt < 4; nt++) {
            int c = ni * 32 + nt * 8 + 2 * qt;
            float p00 = (acc_s[nt][0] < -5e29f) ? 0.f : __expf(acc_s[nt][0] - mn0);
            float p01 = (acc_s[nt][1] < -5e29f) ? 0.f : __expf(acc_s[nt][1] - mn0);
            *reinterpret_cast<__half2*>(sP + lr0 * HPS + c) = __floats2half2_rn(p00, p01);
            ls0 += p00 + p01;
            float p10 = (acc_s[nt][2] < -5e29f) ? 0.f : __expf(acc_s[nt][2] - mn1);
            float p11 = (acc_s[nt][3] < -5e29f) ? 0.f : __expf(acc_s[nt][3] - mn1);
            *reinterpret_cast<__half2*>(sP + lr1 * HPS + c) = __floats2half2_rn(p10, p11);
            ls1 += p10 + p11;
        }
        ls0 += __shfl_xor_sync(0xffffffffu, ls0, 1);
        ls0 += __shfl_xor_sync(0xffffffffu, ls0, 2);
        ls1 += __shfl_xor_sync(0xffffffffu, ls1, 1);
        ls1 += __shfl_xor_sync(0xffffffffu, ls1, 2);
        if (qt == 0) {
            sRSum[lr0 * 2 + ni] = ls0;
            sRSum[lr1 * 2 + ni] = ls1;
        }
        // rescale O accumulators
#pragma unroll
        for (int nt = 0; nt < 8; nt++) {
            acc_o[nt][0] *= f0; acc_o[nt][1] *= f0;
            acc_o[nt][2] *= f1; acc_o[nt][3] *= f1;
        }
        __syncthreads();  // sP + sRSum complete

        if (ni == 0 && qt == 0) {
            int q2 = 1 - p;
            sM[q2 * 64 + lr0] = mn0;
            sL[q2 * 64 + lr0] = sL[p * 64 + lr0] * f0 + sRSum[lr0 * 2] + sRSum[lr0 * 2 + 1];
            sM[q2 * 64 + lr1] = mn1;
            sL[q2 * 64 + lr1] = sL[p * 64 + lr1] * f1 + sRSum[lr1 * 2] + sRSum[lr1 * 2 + 1];
        }

        // ---- O += P V : warp tile 16x64, fp16 m16n8k16, V via ldmatrix.trans ----
#pragma unroll
        for (int ks = 0; ks < 4; ks++) {
            unsigned a[4];
            ldsm_x4(a[0], a[1], a[2], a[3],
                    uP + ((mi * 16 + l15) * HPS + ks * 16 + (lane >> 4) * 8) * 2);
#pragma unroll
            for (int nt = 0; nt < 8; nt++) {
                unsigned bf[2];
                ldsm_x2t(bf[0], bf[1],
                         uVb + ((ks * 16 + l15) * HVS + ni * 64 + nt * 8) * 2);
                mma_f16(acc_o[nt], a, bf);
            }
        }
    }

    __syncthreads();  // final sM/sL (parity 0 after t=15) visible
    float il0 = 1.0f / sL[lr0];
    float il1 = 1.0f / sL[lr1];
    float* o0 = g_o + ((size_t)(b * NN + n0 + lr0)) * DD;
    float* o1 = g_o + ((size_t)(b * NN + n0 + lr1)) * DD;
#pragma unroll
    for (int nt = 0; nt < 8; nt++) {
        int c = ni * 64 + nt * 8 + 2 * qt;
        *reinterpret_cast<float2*>(o0 + c) =
            make_float2(acc_o[nt][0] * il0, acc_o[nt][1] * il0);
        *reinterpret_cast<float2*>(o1 + c) =
            make_float2(acc_o[nt][2] * il1, acc_o[nt][3] * il1);
    }
}

// ---------------- epilogue: out = LN(O + vpe) + v ---------------------------
__global__ __launch_bounds__(256) void epi_kernel(
    const float* __restrict__ gamma, const float* __restrict__ beta,
    float* __restrict__ out) {
    int tid = threadIdx.x;
    int b = blockIdx.y;
    int n = blockIdx.x * 64 + (tid >> 2);
    int part = tid & 3;

    const float* orow = g_o + ((size_t)(b * NN + n)) * DD;
    const float* vper = g_vpe + n * DD;
    float x[32];
    float sum = 0.f, sq = 0.f;
#pragma unroll
    for (int u = 0; u < 32; u += 4) {
        int d = part * 32 + u;
        float4 o4 = *reinterpret_cast<const float4*>(orow + d);
        float4 p4 = *reinterpret_cast<const float4*>(vper + d);
        float4 v;
        v.x = o4.x + p4.x; v.y = o4.y + p4.y;
        v.z = o4.z + p4.z; v.w = o4.w + p4.w;
        x[u] = v.x; x[u + 1] = v.y; x[u + 2] = v.z; x[u + 3] = v.w;
        sum += v.x + v.y + v.z + v.w;
        sq += v.x * v.x + v.y * v.y + v.z * v.z + v.w * v.w;
    }
#pragma unroll
    for (int o = 1; o <= 2; o <<= 1) {
        sum += __shfl_xor_sync(0xffffffffu, sum, o);
        sq += __shfl_xor_sync(0xffffffffu, sq, o);
    }
    float mu = sum * (1.f / 128.f);
    float var = sq * (1.f / 128.f) - mu * mu;
    float rstd = rsqrtf(var + 1e-5f);
    const float* gvr = g_v + ((size_t)(b * NN + n)) * DD;
    float* orow_out = out + ((size_t)(b * NN + n)) * DD;
#pragma unroll
    for (int u = 0; u < 32; u += 4) {
        int d = part * 32 + u;
        float4 gm = *reinterpret_cast<const float4*>(gamma + d);
        float4 bt = *reinterpret_cast<const float4*>(beta + d);
        float4 vv = *reinterpret_cast<const float4*>(gvr + d);
        float4 r4;
        r4.x = (x[u] - mu) * rstd * gm.x + bt.x + vv.x;
        r4.y = (x[u + 1] - mu) * rstd * gm.y + bt.y + vv.y;
        r4.z = (x[u + 2] - mu) * rstd * gm.z + bt.z + vv.z;
        r4.w = (x[u + 3] - mu) * rstd * gm.w + bt.w + vv.w;
        *reinterpret_cast<float4*>(orow_out + d) = r4;
    }
}

// ---------------- launch ---------------------------------------------------
extern "C" void kernel_launch(void* const* d_in, const int* in_sizes, int n_in,
                              void* d_out, int out_size) {
    const float* values = (const float*)d_in[0];
    const int* mask = (const int*)d_in[3];
    const float* vpe = (const float*)d_in[4];
    const float* kpe = (const float*)d_in[5];
    const float* Wv = (const float*)d_in[6];
    const float* Wk = (const float*)d_in[7];
    const float* Wq = (const float*)d_in[8];
    const float* ln_gamma = (const float*)d_in[9];
    const float* ln_beta = (const float*)d_in[10];
    float* out = (float*)d_out;

    static cudaStream_t s2 = nullptr;
    static cudaEvent_t ev_fork = nullptr, ev_kpe = nullptr, ev_vpe = nullptr;
    if (!s2) {
        cudaStreamCreateWithFlags(&s2, cudaStreamNonBlocking);   // default priority
        cudaEventCreateWithFlags(&ev_fork, cudaEventDisableTiming);
        cudaEventCreateWithFlags(&ev_kpe, cudaEventDisableTiming);
        cudaEventCreateWithFlags(&ev_vpe, cudaEventDisableTiming);
        cudaFuncSetAttribute(proj_fused_kernel,
                             cudaFuncAttributeMaxDynamicSharedMemorySize, FPROJ_SMEM);
        cudaFuncSetAttribute(attn_kernel,
                             cudaFuncAttributeMaxDynamicSharedMemorySize, ATTN_SMEM);
    }

    // s2: kpe -> vpe (single launches)
    // s0: proj -> (kpe) attn -> (vpe) epi
    cudaEventRecord(ev_fork, 0);
    cudaStreamWaitEvent(s2, ev_fork, 0);
    kpe_kernel<<<NN * NN / 256, 256, 0, s2>>>(kpe);
    cudaEventRecord(ev_kpe, s2);
    vpe_kernel<<<NN, 256, 0, s2>>>(vpe);
    cudaEventRecord(ev_vpe, s2);

    proj_fused_kernel<<<BB * NN / 64, 256, FPROJ_SMEM>>>(values, Wv, Wk, Wq);
    cudaStreamWaitEvent(0, ev_kpe, 0);
    attn_kernel<<<dim3(NN / 64, BB), 256, ATTN_SMEM>>>(mask);
    cudaStreamWaitEvent(0, ev_vpe, 0);
    epi_kernel<<<dim3(NN / 64, BB), 256>>>(ln_gamma, ln_beta, out);
}

// round 15
// speedup vs baseline: 1.1160x; 1.0018x over previous
#include <cuda_runtime.h>
#include <cuda_fp16.h>

#define BB 8
#define NN 1024
#define DD 128

// ---------------- scratch (device globals; no allocation allowed) ----------
__device__ float g_v[BB * NN * DD];
__device__ float g_o[BB * NN * DD];
__device__ __half g_vh[BB * NN * DD];
__device__ __half g_kh[BB * NN * DD];
__device__ __half g_qh[BB * NN * DD];   // pre-scaled by 1/sqrt(D)
__device__ float g_kpe[NN * NN];
__device__ float g_vpe[NN * DD];

// ---------------- asm helpers ----------------------------------------------
__device__ __forceinline__ unsigned smem_u32(const void* p) {
    unsigned a;
    asm("{ .reg .u64 t; cvta.to.shared.u64 t, %1; cvt.u32.u64 %0, t; }"
        : "=r"(a) : "l"(p));
    return a;
}
__device__ __forceinline__ void ldsm_x4(unsigned& a0, unsigned& a1,
                                        unsigned& a2, unsigned& a3, unsigned addr) {
    asm volatile("ldmatrix.sync.aligned.m8n8.x4.shared.b16 {%0,%1,%2,%3}, [%4];"
                 : "=r"(a0), "=r"(a1), "=r"(a2), "=r"(a3) : "r"(addr));
}
__device__ __forceinline__ void ldsm_x2(unsigned& b0, unsigned& b1, unsigned addr) {
    asm volatile("ldmatrix.sync.aligned.m8n8.x2.shared.b16 {%0,%1}, [%2];"
                 : "=r"(b0), "=r"(b1) : "r"(addr));
}
__device__ __forceinline__ void ldsm_x2t(unsigned& b0, unsigned& b1, unsigned addr) {
    asm volatile("ldmatrix.sync.aligned.m8n8.x2.trans.shared.b16 {%0,%1}, [%2];"
                 : "=r"(b0), "=r"(b1) : "r"(addr));
}
__device__ __forceinline__ void mma_f16(float d[4], const unsigned a[4],
                                        const unsigned b[2]) {
    asm("mma.sync.aligned.m16n8k16.row.col.f32.f16.f16.f32 "
        "{%0,%1,%2,%3}, {%4,%5,%6,%7}, {%8,%9}, {%0,%1,%2,%3};"
        : "+f"(d[0]), "+f"(d[1]), "+f"(d[2]), "+f"(d[3])
        : "r"(a[0]), "r"(a[1]), "r"(a[2]), "r"(a[3]), "r"(b[0]), "r"(b[1]));
}
__device__ __forceinline__ void cp16(unsigned dst, const void* src) {
    asm volatile("cp.async.cg.shared.global [%0], [%1], 16;"
                 :: "r"(dst), "l"(src));
}
__device__ __forceinline__ float4 ldcs4(const float4* p) {
    float4 v;
    asm volatile("ld.global.cs.v4.f32 {%0,%1,%2,%3}, [%4];"
                 : "=f"(v.x), "=f"(v.y), "=f"(v.z), "=f"(v.w) : "l"(p));
    return v;
}

// ---------------- kpe[n,m] = sum_d keys_pos_enc[n,m,d] ---------------------
// warp-per-32-rows (4 groups of 8), coalesced 512B rows, MLP 8, streaming.
__global__ __launch_bounds__(256) void kpe_kernel(const float* __restrict__ kp) {
    int gwarp = (blockIdx.x * 256 + threadIdx.x) >> 5;
    int lane = threadIdx.x & 31;
#pragma unroll
    for (int grp = 0; grp < 4; grp++) {
        size_t row0 = (size_t)gwarp * 32 + grp * 8;
        const float4* p = reinterpret_cast<const float4*>(kp) + row0 * 32 + lane;
        float s[8];
#pragma unroll
        for (int i = 0; i < 8; i++) {
            float4 v = ldcs4(p + i * 32);
            s[i] = (v.x + v.y) + (v.z + v.w);
        }
#pragma unroll
        for (int i = 0; i < 8; i++) {
#pragma unroll
            for (int o = 16; o >= 1; o >>= 1)
                s[i] += __shfl_xor_sync(0xffffffffu, s[i], o);
        }
        float out = 0.f;
#pragma unroll
        for (int i = 0; i < 8; i++)
            if (lane == i) out = s[i];
        if (lane < 8) g_kpe[row0 + lane] = out;
    }
}

// ---------------- vpe[n,d] = sum_m values_pos_enc[n,m,d] -------------------
// single launch (1024 CTAs), 8 independent acc chains, streaming loads.
__global__ void vpe_kernel(const float* __restrict__ vp) {
    __shared__ float4 red[8][32];
    int n = blockIdx.x;
    int g = threadIdx.x >> 5, lane = threadIdx.x & 31;
    const float4* base = reinterpret_cast<const float4*>(vp + (size_t)n * NN * DD);
    float4 acc[8];
#pragma unroll
    for (int i = 0; i < 8; i++) acc[i] = make_float4(0.f, 0.f, 0.f, 0.f);
    for (int m = g; m < NN; m += 64) {
#pragma unroll
        for (int i = 0; i < 8; i++) {
            float4 v = ldcs4(base + (m + i * 8) * 32 + lane);
            acc[i].x += v.x; acc[i].y += v.y; acc[i].z += v.z; acc[i].w += v.w;
        }
    }
#pragma unroll
    for (int i = 1; i < 8; i++) {
        acc[0].x += acc[i].x; acc[0].y += acc[i].y;
        acc[0].z += acc[i].z; acc[0].w += acc[i].w;
    }
    red[g][lane] = acc[0];
    __syncthreads();
    if (g == 0) {
        float4 a = red[0][lane];
#pragma unroll
        for (int i = 1; i < 8; i++) {
            float4 b = red[i][lane];
            a.x += b.x; a.y += b.y; a.z += b.z; a.w += b.w;
        }
        reinterpret_cast<float4*>(g_vpe + n * DD)[lane] = a;
    }
}

// ---------------- fused projection: v = X Wv^T; k = v Wk^T; q = v Wq^T -----
#define FPROJ_SMEM ((64 * 132 + 64 * 132 + 128 * 132) * 4)

__device__ __forceinline__ void gemm_64x128(const float* __restrict__ sA,
                                            const float* __restrict__ sWt,
                                            int ty, int tx, float acc[4][8]) {
#pragma unroll
    for (int i = 0; i < 4; i++)
#pragma unroll
        for (int j = 0; j < 8; j++) acc[i][j] = 0.f;
    for (int kk = 0; kk < 128; kk += 4) {
        float4 a[4];
#pragma unroll
        for (int i = 0; i < 4; i++)
            a[i] = *reinterpret_cast<const float4*>(sA + (ty * 4 + i) * 132 + kk);
#pragma unroll
        for (int t = 0; t < 4; t++) {
            float4 b0 = *reinterpret_cast<const float4*>(sWt + (kk + t) * 132 + tx * 8);
            float4 b1 = *reinterpret_cast<const float4*>(sWt + (kk + t) * 132 + tx * 8 + 4);
#pragma unroll
            for (int i = 0; i < 4; i++) {
                float aa = reinterpret_cast<const float*>(&a[i])[t];
                acc[i][0] += aa * b0.x; acc[i][1] += aa * b0.y;
                acc[i][2] += aa * b0.z; acc[i][3] += aa * b0.w;
                acc[i][4] += aa * b1.x; acc[i][5] += aa * b1.y;
                acc[i][6] += aa * b1.z; acc[i][7] += aa * b1.w;
            }
        }
    }
}

__device__ __forceinline__ void load_wt(const float* __restrict__ W,
                                        float* __restrict__ sWt, int tid) {
    for (int it = tid; it < 128 * 32; it += 256) {
        int o = it >> 5, e4 = it & 31;
        float4 v = *reinterpret_cast<const float4*>(W + o * DD + e4 * 4);
        sWt[(e4 * 4 + 0) * 132 + o] = v.x;
        sWt[(e4 * 4 + 1) * 132 + o] = v.y;
        sWt[(e4 * 4 + 2) * 132 + o] = v.z;
        sWt[(e4 * 4 + 3) * 132 + o] = v.w;
    }
}

__device__ __forceinline__ void store_half8(__half* dst, const float* a, float sc) {
#pragma unroll
    for (int j = 0; j < 4; j++) {
        __half2 h = __floats2half2_rn(a[2 * j] * sc, a[2 * j + 1] * sc);
        *reinterpret_cast<__half2*>(dst + 2 * j) = h;
    }
}

__global__ __launch_bounds__(256) void proj_fused_kernel(
    const float* __restrict__ X, const float* __restrict__ Wv,
    const float* __restrict__ Wk, const float* __restrict__ Wq) {
    extern __shared__ float sm[];
    float* sX = sm;
    float* sV = sm + 64 * 132;
    float* sWt = sm + 2 * 64 * 132;
    const float inv_s = 0.088388347648318447f;

    int tid = threadIdx.x;
    int row0 = blockIdx.x * 64;
    int ty = tid >> 4, tx = tid & 15;
    float acc[4][8];

    for (int it = tid; it < 64 * 32; it += 256) {
        int r = it >> 5, c4 = it & 31;
        float4 v = *reinterpret_cast<const float4*>(X + (size_t)(row0 + r) * DD + c4 * 4);
        *reinterpret_cast<float4*>(sX + r * 132 + c4 * 4) = v;
    }
    load_wt(Wv, sWt, tid);
    __syncthreads();

    gemm_64x128(sX, sWt, ty, tx, acc);
    __syncthreads();
#pragma unroll
    for (int i = 0; i < 4; i++) {
        int r = ty * 4 + i;
        size_t go = (size_t)(row0 + r) * DD + tx * 8;
        float4 lo = make_float4(acc[i][0], acc[i][1], acc[i][2], acc[i][3]);
        float4 hi = make_float4(acc[i][4], acc[i][5], acc[i][6], acc[i][7]);
        *reinterpret_cast<float4*>(sV + r * 132 + tx * 8) = lo;
        *reinterpret_cast<float4*>(sV + r * 132 + tx * 8 + 4) = hi;
        *reinterpret_cast<float4*>(g_v + go) = lo;
        *reinterpret_cast<float4*>(g_v + go + 4) = hi;
        store_half8(g_vh + go, acc[i], 1.0f);
    }
    load_wt(Wk, sWt, tid);
    __syncthreads();

    gemm_64x128(sV, sWt, ty, tx, acc);
#pragma unroll
    for (int i = 0; i < 4; i++) {
        size_t go = (size_t)(row0 + ty * 4 + i) * DD + tx * 8;
        store_half8(g_kh + go, acc[i], 1.0f);
    }
    __syncthreads();
    load_wt(Wq, sWt, tid);
    __syncthreads();

    gemm_64x128(sV, sWt, ty, tx, acc);
#pragma unroll
    for (int i = 0; i < 4; i++) {
        size_t go = (size_t)(row0 + ty * 4 + i) * DD + tx * 8;
        store_half8(g_qh + go, acc[i], inv_s);   // pre-scaled q
    }
}

// ---------------- fp16 tensor-core flash attention ---------------------------
// RACE FIX vs rounds 7-13: a __syncthreads() at the top of the tile loop,
// BEFORE issuing cp.async into buffer q2 — that buffer is the one read by the
// previous iteration's PV mma; without the barrier a fast warp could overwrite
// it while a slow warp was still reading (source of the post-timing divergence).
#define HQS 136
#define HKS 136
#define HVS 136
#define HPS 72
#define ATTN_SMEM ((64*HQS + 2*64*HKS + 2*64*HVS + 64*HPS) * 2 + 512 * 4)

__global__ __launch_bounds__(256) void attn_kernel(const int* __restrict__ mask) {
    extern __shared__ __half hsm[];
    __half* sQ = hsm;                         // 64 x 136
    __half* sK = sQ + 64 * HQS;               // 2 x 64 x 136
    __half* sV = sK + 2 * 64 * HKS;           // 2 x 64 x 136
    __half* sP = sV + 2 * 64 * HVS;           // 64 x 72
    float* sM = reinterpret_cast<float*>(sP + 64 * HPS);  // 2 x 64
    float* sL = sM + 128;                     // 2 x 64
    float* sRMax = sL + 128;                  // 64 x 2
    float* sRSum = sRMax + 128;               // 64 x 2

    int tid = threadIdx.x;
    int b = blockIdx.y;
    int n0 = blockIdx.x * 64;
    int w = tid >> 5, lane = tid & 31;
    int mi = w & 3, ni = w >> 2;
    int qg = lane >> 2, qt = lane & 3;
    const float inv_s = 0.088388347648318447f;

    unsigned uQ = smem_u32(sQ);
    unsigned uK = smem_u32(sK);
    unsigned uV = smem_u32(sV);
    unsigned uP = smem_u32(sP);
    int l15 = lane & 15, l7 = lane & 7;

    // ---- load Q tile (fp16, already pre-scaled) ----
    for (int it = tid; it < 64 * 16; it += 256) {
        int r = it >> 4, c8 = it & 15;
        uint4 v = *reinterpret_cast<const uint4*>(
            g_qh + ((size_t)(b * NN + n0 + r)) * DD + c8 * 8);
        *reinterpret_cast<uint4*>(sQ + r * HQS + c8 * 8) = v;
    }
    if (tid < 64) { sM[tid] = -1e30f; sL[tid] = 0.f; }

    // ---- prologue: cp.async tile 0 into buffer 0 ----
    {
        const __half* kb = g_kh + ((size_t)(b * NN)) * DD;
        const __half* vb = g_vh + ((size_t)(b * NN)) * DD;
        for (int it = tid; it < 1024; it += 256) {
            int r = it >> 4, c16 = it & 15;
            cp16(uK + (r * HKS + c16 * 8) * 2, kb + r * DD + c16 * 8);
            cp16(uV + (r * HVS + c16 * 8) * 2, vb + r * DD + c16 * 8);
        }
        asm volatile("cp.async.commit_group;");
    }

    int lr0 = mi * 16 + qg, lr1 = lr0 + 8;

    float acc_o[8][4];
#pragma unroll
    for (int i = 0; i < 8; i++)
#pragma unroll
        for (int j = 0; j < 4; j++) acc_o[i][j] = 0.f;

    for (int t = 0; t < 16; t++) {
        int p = t & 1;
        int m0 = t * 64;
        unsigned uKb = uK + p * (64 * HKS * 2);
        unsigned uVb = uV + p * (64 * HVS * 2);

        // RACE FIX: all warps must be done with the previous iteration's reads
        // of buffer q2 before any warp overwrites it via cp.async.
        __syncthreads();

        // prefetch tile t+1 into other buffer, then wait for tile t
        if (t < 15) {
            int q2 = 1 - p;
            const __half* kb = g_kh + ((size_t)(b * NN + m0 + 64)) * DD;
            const __half* vb = g_vh + ((size_t)(b * NN + m0 + 64)) * DD;
            unsigned dK = uK + q2 * (64 * HKS * 2);
            unsigned dV = uV + q2 * (64 * HVS * 2);
            for (int it = tid; it < 1024; it += 256) {
                int r = it >> 4, c16 = it & 15;
                cp16(dK + (r * HKS + c16 * 8) * 2, kb + r * DD + c16 * 8);
                cp16(dV + (r * HVS + c16 * 8) * 2, vb + r * DD + c16 * 8);
            }
            asm volatile("cp.async.commit_group;");
            asm volatile("cp.async.wait_group 1;");
        } else {
            asm volatile("cp.async.wait_group 0;");
        }
        __syncthreads();   // tile t K/V visible to all warps

        // ---- prefetch kpe/mask rows (overlaps S mma) ----
        const float* kp0 = g_kpe + (size_t)(n0 + lr0) * NN + m0 + ni * 32;
        const float* kp1 = g_kpe + (size_t)(n0 + lr1) * NN + m0 + ni * 32;
        const int* mr0 = mask + ((size_t)b * NN + n0 + lr0) * NN + m0 + ni * 32;
        const int* mr1 = mask + ((size_t)b * NN + n0 + lr1) * NN + m0 + ni * 32;
        float2 kv0[4], kv1[4];
        int2 mv0[4], mv1[4];
#pragma unroll
        for (int nt = 0; nt < 4; nt++) {
            int c = nt * 8 + 2 * qt;
            kv0[nt] = *reinterpret_cast<const float2*>(kp0 + c);
            kv1[nt] = *reinterpret_cast<const float2*>(kp1 + c);
            mv0[nt] = *reinterpret_cast<const int2*>(mr0 + c);
            mv1[nt] = *reinterpret_cast<const int2*>(mr1 + c);
        }

        // ---- S = Q K^T : warp tile 16x32, fp16 m16n8k16 ----
        float acc_s[4][4];
#pragma unroll
        for (int i = 0; i < 4; i++)
#pragma unroll
            for (int j = 0; j < 4; j++) acc_s[i][j] = 0.f;
#pragma unroll
        for (int ks = 0; ks < 8; ks++) {
            unsigned a[4];
            ldsm_x4(a[0], a[1], a[2], a[3],
                    uQ + ((mi * 16 + l15) * HQS + ks * 16 + (lane >> 4) * 8) * 2);
#pragma unroll
            for (int nt = 0; nt < 4; nt++) {
                unsigned bf[2];
                ldsm_x2(bf[0], bf[1],
                        uKb + ((ni * 32 + nt * 8 + l7) * HKS + ks * 16 +
                               ((lane >> 3) & 1) * 8) * 2);
                mma_f16(acc_s[nt], a, bf);
            }
        }

        // ---- + kpe/sqrt(D), mask; segment max ----
        float lmax0 = -1e30f, lmax1 = -1e30f;
#pragma unroll
        for (int nt = 0; nt < 4; nt++) {
            float e00 = acc_s[nt][0] + kv0[nt].x * inv_s; if (mv0[nt].x == 0) e00 = -1e30f;
            float e01 = acc_s[nt][1] + kv0[nt].y * inv_s; if (mv0[nt].y == 0) e01 = -1e30f;
            acc_s[nt][0] = e00; acc_s[nt][1] = e01;
            lmax0 = fmaxf(lmax0, fmaxf(e00, e01));
            float e10 = acc_s[nt][2] + kv1[nt].x * inv_s; if (mv1[nt].x == 0) e10 = -1e30f;
            float e11 = acc_s[nt][3] + kv1[nt].y * inv_s; if (mv1[nt].y == 0) e11 = -1e30f;
            acc_s[nt][2] = e10; acc_s[nt][3] = e11;
            lmax1 = fmaxf(lmax1, fmaxf(e10, e11));
        }
        lmax0 = fmaxf(lmax0, __shfl_xor_sync(0xffffffffu, lmax0, 1));
        lmax0 = fmaxf(lmax0, __shfl_xor_sync(0xffffffffu, lmax0, 2));
        lmax1 = fmaxf(lmax1, __shfl_xor_sync(0xffffffffu, lmax1, 1));
        lmax1 = fmaxf(lmax1, __shfl_xor_sync(0xffffffffu, lmax1, 2));
        if (qt == 0) {
            sRMax[lr0 * 2 + ni] = lmax0;
            sRMax[lr1 * 2 + ni] = lmax1;
        }
        __syncthreads();

        // ---- online softmax; write P (fp16) ----
        float mo0 = sM[p * 64 + lr0], mo1 = sM[p * 64 + lr1];
        float mn0 = fmaxf(mo0, fmaxf(sRMax[lr0 * 2], sRMax[lr0 * 2 + 1]));
        float mn1 = fmaxf(mo1, fmaxf(sRMax[lr1 * 2], sRMax[lr1 * 2 + 1]));
        float f0 = __expf(mo0 - mn0), f1 = __expf(mo1 - mn1);
        float ls0 = 0.f, ls1 = 0.f;
#pragma unroll
        for (int nt = 0; nt < 4; nt++) {
            int c = ni * 32 + nt * 8 + 2 * qt;
            float p00 = (acc_s[nt][0] < -5e29f) ? 0.f : __expf(acc_s[nt][0] - mn0);
            float p01 = (acc_s[nt][1] < -5e29f) ? 0.f : __expf(acc_s[nt][1] - mn0);
            *reinterpret_cast<__half2*>(sP + lr0 * HPS + c) = __floats2half2_rn(p00, p01);
            ls0 += p00 + p01;
            float p10 = (acc_s[nt][2] < -5e29f) ? 0.f : __expf(acc_s[nt][2] - mn1);
            float p11 = (acc_s[nt][3] < -5e29f) ? 0.f : __expf(acc_s[nt][3] - mn1);
            *reinterpret_cast<__half2*>(sP + lr1 * HPS + c) = __floats2half2_rn(p10, p11);
            ls1 += p10 + p11;
        }
        ls0 += __shfl_xor_sync(0xffffffffu, ls0, 1);
        ls0 += __shfl_xor_sync(0xffffffffu, ls0, 2);
        ls1 += __shfl_xor_sync(0xffffffffu, ls1, 1);
        ls1 += __shfl_xor_sync(0xffffffffu, ls1, 2);
        if (qt == 0) {
            sRSum[lr0 * 2 + ni] = ls0;
            sRSum[lr1 * 2 + ni] = ls1;
        }
        // rescale O accumulators
#pragma unroll
        for (int nt = 0; nt < 8; nt++) {
            acc_o[nt][0] *= f0; acc_o[nt][1] *= f0;
            acc_o[nt][2] *= f1; acc_o[nt][3] *= f1;
        }
        __syncthreads();  // sP + sRSum complete

        if (ni == 0 && qt == 0) {
            int q2 = 1 - p;
            sM[q2 * 64 + lr0] = mn0;
            sL[q2 * 64 + lr0] = sL[p * 64 + lr0] * f0 + sRSum[lr0 * 2] + sRSum[lr0 * 2 + 1];
            sM[q2 * 64 + lr1] = mn1;
            sL[q2 * 64 + lr1] = sL[p * 64 + lr1] * f1 + sRSum[lr1 * 2] + sRSum[lr1 * 2 + 1];
        }

        // ---- O += P V : warp tile 16x64, fp16 m16n8k16, V via ldmatrix.trans ----
#pragma unroll
        for (int ks = 0; ks < 4; ks++) {
            unsigned a[4];
            ldsm_x4(a[0], a[1], a[2], a[3],
                    uP + ((mi * 16 + l15) * HPS + ks * 16 + (lane >> 4) * 8) * 2);
#pragma unroll
            for (int nt = 0; nt < 8; nt++) {
                unsigned bf[2];
                ldsm_x2t(bf[0], bf[1],
                         uVb + ((ks * 16 + l15) * HVS + ni * 64 + nt * 8) * 2);
                mma_f16(acc_o[nt], a, bf);
            }
        }
    }

    __syncthreads();  // final sM/sL (parity 0 after t=15) visible
    float il0 = 1.0f / sL[lr0];
    float il1 = 1.0f / sL[lr1];
    float* o0 = g_o + ((size_t)(b * NN + n0 + lr0)) * DD;
    float* o1 = g_o + ((size_t)(b * NN + n0 + lr1)) * DD;
#pragma unroll
    for (int nt = 0; nt < 8; nt++) {
        int c = ni * 64 + nt * 8 + 2 * qt;
        *reinterpret_cast<float2*>(o0 + c) =
            make_float2(acc_o[nt][0] * il0, acc_o[nt][1] * il0);
        *reinterpret_cast<float2*>(o1 + c) =
            make_float2(acc_o[nt][2] * il1, acc_o[nt][3] * il1);
    }
}

// ---------------- epilogue: out = LN(O + vpe) + v ---------------------------
__global__ __launch_bounds__(256) void epi_kernel(
    const float* __restrict__ gamma, const float* __restrict__ beta,
    float* __restrict__ out) {
    int tid = threadIdx.x;
    int b = blockIdx.y;
    int n = blockIdx.x * 64 + (tid >> 2);
    int part = tid & 3;

    const float* orow = g_o + ((size_t)(b * NN + n)) * DD;
    const float* vper = g_vpe + n * DD;
    float x[32];
    float sum = 0.f, sq = 0.f;
#pragma unroll
    for (int u = 0; u < 32; u += 4) {
        int d = part * 32 + u;
        float4 o4 = *reinterpret_cast<const float4*>(orow + d);
        float4 p4 = *reinterpret_cast<const float4*>(vper + d);
        float4 v;
        v.x = o4.x + p4.x; v.y = o4.y + p4.y;
        v.z = o4.z + p4.z; v.w = o4.w + p4.w;
        x[u] = v.x; x[u + 1] = v.y; x[u + 2] = v.z; x[u + 3] = v.w;
        sum += v.x + v.y + v.z + v.w;
        sq += v.x * v.x + v.y * v.y + v.z * v.z + v.w * v.w;
    }
#pragma unroll
    for (int o = 1; o <= 2; o <<= 1) {
        sum += __shfl_xor_sync(0xffffffffu, sum, o);
        sq += __shfl_xor_sync(0xffffffffu, sq, o);
    }
    float mu = sum * (1.f / 128.f);
    float var = sq * (1.f / 128.f) - mu * mu;
    float rstd = rsqrtf(var + 1e-5f);
    const float* gvr = g_v + ((size_t)(b * NN + n)) * DD;
    float* orow_out = out + ((size_t)(b * NN + n)) * DD;
#pragma unroll
    for (int u = 0; u < 32; u += 4) {
        int d = part * 32 + u;
        float4 gm = *reinterpret_cast<const float4*>(gamma + d);
        float4 bt = *reinterpret_cast<const float4*>(beta + d);
        float4 vv = *reinterpret_cast<const float4*>(gvr + d);
        float4 r4;
        r4.x = (x[u] - mu) * rstd * gm.x + bt.x + vv.x;
        r4.y = (x[u + 1] - mu) * rstd * gm.y + bt.y + vv.y;
        r4.z = (x[u + 2] - mu) * rstd * gm.z + bt.z + vv.z;
        r4.w = (x[u + 3] - mu) * rstd * gm.w + bt.w + vv.w;
        *reinterpret_cast<float4*>(orow_out + d) = r4;
    }
}

// ---------------- launch ---------------------------------------------------
extern "C" void kernel_launch(void* const* d_in, const int* in_sizes, int n_in,
                              void* d_out, int out_size) {
    const float* values = (const float*)d_in[0];
    const int* mask = (const int*)d_in[3];
    const float* vpe = (const float*)d_in[4];
    const float* kpe = (const float*)d_in[5];
    const float* Wv = (const float*)d_in[6];
    const float* Wk = (const float*)d_in[7];
    const float* Wq = (const float*)d_in[8];
    const float* ln_gamma = (const float*)d_in[9];
    const float* ln_beta = (const float*)d_in[10];
    float* out = (float*)d_out;

    static cudaStream_t s2 = nullptr;
    static cudaEvent_t ev_fork = nullptr, ev_kpe = nullptr, ev_vpe = nullptr;
    if (!s2) {
        cudaStreamCreateWithFlags(&s2, cudaStreamNonBlocking);   // default priority
        cudaEventCreateWithFlags(&ev_fork, cudaEventDisableTiming);
        cudaEventCreateWithFlags(&ev_kpe, cudaEventDisableTiming);
        cudaEventCreateWithFlags(&ev_vpe, cudaEventDisableTiming);
        cudaFuncSetAttribute(proj_fused_kernel,
                             cudaFuncAttributeMaxDynamicSharedMemorySize, FPROJ_SMEM);
        cudaFuncSetAttribute(attn_kernel,
                             cudaFuncAttributeMaxDynamicSharedMemorySize, ATTN_SMEM);
    }

    // s2: kpe -> vpe (single launches)
    // s0: proj -> (kpe) attn -> (vpe) epi
    cudaEventRecord(ev_fork, 0);
    cudaStreamWaitEvent(s2, ev_fork, 0);
    kpe_kernel<<<NN * NN / 256, 256, 0, s2>>>(kpe);
    cudaEventRecord(ev_kpe, s2);
    vpe_kernel<<<NN, 256, 0, s2>>>(vpe);
    cudaEventRecord(ev_vpe, s2);

    proj_fused_kernel<<<BB * NN / 64, 256, FPROJ_SMEM>>>(values, Wv, Wk, Wq);
    cudaStreamWaitEvent(0, ev_kpe, 0);
    attn_kernel<<<dim3(NN / 64, BB), 256, ATTN_SMEM>>>(mask);
    cudaStreamWaitEvent(0, ev_vpe, 0);
    epi_kernel<<<dim3(NN / 64, BB), 256>>>(ln_gamma, ln_beta, out);
}

// round 16
// speedup vs baseline: 1.1320x; 1.0144x over previous
#include <cuda_runtime.h>
#include <cuda_fp16.h>

#define BB 8
#define NN 1024
#define DD 128

// ---------------- scratch (device globals; no allocation allowed) ----------
__device__ float g_v[BB * NN * DD];
__device__ float g_o[BB * NN * DD];
__device__ __half g_vh[BB * NN * DD];
__device__ __half g_kh[BB * NN * DD];
__device__ __half g_qh[BB * NN * DD];   // pre-scaled by 1/sqrt(D)
__device__ float g_kpe[NN * NN];
__device__ float g_vpe[NN * DD];

// ---------------- asm helpers ----------------------------------------------
__device__ __forceinline__ unsigned smem_u32(const void* p) {
    unsigned a;
    asm("{ .reg .u64 t; cvta.to.shared.u64 t, %1; cvt.u32.u64 %0, t; }"
        : "=r"(a) : "l"(p));
    return a;
}
__device__ __forceinline__ void ldsm_x4(unsigned& a0, unsigned& a1,
                                        unsigned& a2, unsigned& a3, unsigned addr) {
    asm volatile("ldmatrix.sync.aligned.m8n8.x4.shared.b16 {%0,%1,%2,%3}, [%4];"
                 : "=r"(a0), "=r"(a1), "=r"(a2), "=r"(a3) : "r"(addr));
}
__device__ __forceinline__ void ldsm_x2(unsigned& b0, unsigned& b1, unsigned addr) {
    asm volatile("ldmatrix.sync.aligned.m8n8.x2.shared.b16 {%0,%1}, [%2];"
                 : "=r"(b0), "=r"(b1) : "r"(addr));
}
__device__ __forceinline__ void ldsm_x2t(unsigned& b0, unsigned& b1, unsigned addr) {
    asm volatile("ldmatrix.sync.aligned.m8n8.x2.trans.shared.b16 {%0,%1}, [%2];"
                 : "=r"(b0), "=r"(b1) : "r"(addr));
}
__device__ __forceinline__ void mma_f16(float d[4], const unsigned a[4],
                                        const unsigned b[2]) {
    asm("mma.sync.aligned.m16n8k16.row.col.f32.f16.f16.f32 "
        "{%0,%1,%2,%3}, {%4,%5,%6,%7}, {%8,%9}, {%0,%1,%2,%3};"
        : "+f"(d[0]), "+f"(d[1]), "+f"(d[2]), "+f"(d[3])
        : "r"(a[0]), "r"(a[1]), "r"(a[2]), "r"(a[3]), "r"(b[0]), "r"(b[1]));
}
__device__ __forceinline__ void cp16(unsigned dst, const void* src) {
    asm volatile("cp.async.cg.shared.global [%0], [%1], 16;"
                 :: "r"(dst), "l"(src));
}
__device__ __forceinline__ float4 ldcs4(const float4* p) {
    float4 v;
    asm volatile("ld.global.cs.v4.f32 {%0,%1,%2,%3}, [%4];"
                 : "=f"(v.x), "=f"(v.y), "=f"(v.z), "=f"(v.w) : "l"(p));
    return v;
}

// ---------------- kpe[n,m] = sum_d keys_pos_enc[n,m,d] ---------------------
// warp-per-32-rows (4 groups of 8), coalesced 512B rows, streaming loads.
// SOFTWARE PIPELINE (round 16): group g+1's loads are issued BEFORE group g's
// shuffle-reduce tree, so the 5-deep SHFL chain hides under DRAM latency and
// the warp's load duty cycle stays high. Per-row arithmetic order unchanged.
__global__ __launch_bounds__(256) void kpe_kernel(const float* __restrict__ kp) {
    int gwarp = (blockIdx.x * 256 + threadIdx.x) >> 5;
    int lane = threadIdx.x & 31;
    const float4* base = reinterpret_cast<const float4*>(kp)
                         + (size_t)gwarp * 32 * 32 + lane;
    float4 v[8];
#pragma unroll
    for (int i = 0; i < 8; i++) v[i] = ldcs4(base + i * 32);   // group 0 in flight
#pragma unroll
    for (int g = 0; g < 4; g++) {
        float s[8];
#pragma unroll
        for (int i = 0; i < 8; i++)
            s[i] = (v[i].x + v[i].y) + (v[i].z + v[i].w);
        if (g < 3) {   // issue next group's loads before the shuffle phase
#pragma unroll
            for (int i = 0; i < 8; i++)
                v[i] = ldcs4(base + (g + 1) * 8 * 32 + i * 32);
        }
#pragma unroll
        for (int i = 0; i < 8; i++) {
#pragma unroll
            for (int o = 16; o >= 1; o >>= 1)
                s[i] += __shfl_xor_sync(0xffffffffu, s[i], o);
        }
        float out = 0.f;
#pragma unroll
        for (int i = 0; i < 8; i++)
            if (lane == i) out = s[i];
        if (lane < 8) g_kpe[(size_t)gwarp * 32 + g * 8 + lane] = out;
    }
}

// ---------------- vpe[n,d] = sum_m values_pos_enc[n,m,d] -------------------
// single launch (1024 CTAs), 8 independent acc chains, streaming loads.
__global__ void vpe_kernel(const float* __restrict__ vp) {
    __shared__ float4 red[8][32];
    int n = blockIdx.x;
    int g = threadIdx.x >> 5, lane = threadIdx.x & 31;
    const float4* base = reinterpret_cast<const float4*>(vp + (size_t)n * NN * DD);
    float4 acc[8];
#pragma unroll
    for (int i = 0; i < 8; i++) acc[i] = make_float4(0.f, 0.f, 0.f, 0.f);
    for (int m = g; m < NN; m += 64) {
#pragma unroll
        for (int i = 0; i < 8; i++) {
            float4 v = ldcs4(base + (m + i * 8) * 32 + lane);
            acc[i].x += v.x; acc[i].y += v.y; acc[i].z += v.z; acc[i].w += v.w;
        }
    }
#pragma unroll
    for (int i = 1; i < 8; i++) {
        acc[0].x += acc[i].x; acc[0].y += acc[i].y;
        acc[0].z += acc[i].z; acc[0].w += acc[i].w;
    }
    red[g][lane] = acc[0];
    __syncthreads();
    if (g == 0) {
        float4 a = red[0][lane];
#pragma unroll
        for (int i = 1; i < 8; i++) {
            float4 b = red[i][lane];
            a.x += b.x; a.y += b.y; a.z += b.z; a.w += b.w;
        }
        reinterpret_cast<float4*>(g_vpe + n * DD)[lane] = a;
    }
}

// ---------------- fused projection: v = X Wv^T; k = v Wk^T; q = v Wq^T -----
#define FPROJ_SMEM ((64 * 132 + 64 * 132 + 128 * 132) * 4)

__device__ __forceinline__ void gemm_64x128(const float* __restrict__ sA,
                                            const float* __restrict__ sWt,
                                            int ty, int tx, float acc[4][8]) {
#pragma unroll
    for (int i = 0; i < 4; i++)
#pragma unroll
        for (int j = 0; j < 8; j++) acc[i][j] = 0.f;
    for (int kk = 0; kk < 128; kk += 4) {
        float4 a[4];
#pragma unroll
        for (int i = 0; i < 4; i++)
            a[i] = *reinterpret_cast<const float4*>(sA + (ty * 4 + i) * 132 + kk);
#pragma unroll
        for (int t = 0; t < 4; t++) {
            float4 b0 = *reinterpret_cast<const float4*>(sWt + (kk + t) * 132 + tx * 8);
            float4 b1 = *reinterpret_cast<const float4*>(sWt + (kk + t) * 132 + tx * 8 + 4);
#pragma unroll
            for (int i = 0; i < 4; i++) {
                float aa = reinterpret_cast<const float*>(&a[i])[t];
                acc[i][0] += aa * b0.x; acc[i][1] += aa * b0.y;
                acc[i][2] += aa * b0.z; acc[i][3] += aa * b0.w;
                acc[i][4] += aa * b1.x; acc[i][5] += aa * b1.y;
                acc[i][6] += aa * b1.z; acc[i][7] += aa * b1.w;
            }
        }
    }
}

__device__ __forceinline__ void load_wt(const float* __restrict__ W,
                                        float* __restrict__ sWt, int tid) {
    for (int it = tid; it < 128 * 32; it += 256) {
        int o = it >> 5, e4 = it & 31;
        float4 v = *reinterpret_cast<const float4*>(W + o * DD + e4 * 4);
        sWt[(e4 * 4 + 0) * 132 + o] = v.x;
        sWt[(e4 * 4 + 1) * 132 + o] = v.y;
        sWt[(e4 * 4 + 2) * 132 + o] = v.z;
        sWt[(e4 * 4 + 3) * 132 + o] = v.w;
    }
}

__device__ __forceinline__ void store_half8(__half* dst, const float* a, float sc) {
#pragma unroll
    for (int j = 0; j < 4; j++) {
        __half2 h = __floats2half2_rn(a[2 * j] * sc, a[2 * j + 1] * sc);
        *reinterpret_cast<__half2*>(dst + 2 * j) = h;
    }
}

__global__ __launch_bounds__(256) void proj_fused_kernel(
    const float* __restrict__ X, const float* __restrict__ Wv,
    const float* __restrict__ Wk, const float* __restrict__ Wq) {
    extern __shared__ float sm[];
    float* sX = sm;
    float* sV = sm + 64 * 132;
    float* sWt = sm + 2 * 64 * 132;
    const float inv_s = 0.088388347648318447f;

    int tid = threadIdx.x;
    int row0 = blockIdx.x * 64;
    int ty = tid >> 4, tx = tid & 15;
    float acc[4][8];

    for (int it = tid; it < 64 * 32; it += 256) {
        int r = it >> 5, c4 = it & 31;
        float4 v = *reinterpret_cast<const float4*>(X + (size_t)(row0 + r) * DD + c4 * 4);
        *reinterpret_cast<float4*>(sX + r * 132 + c4 * 4) = v;
    }
    load_wt(Wv, sWt, tid);
    __syncthreads();

    gemm_64x128(sX, sWt, ty, tx, acc);
    __syncthreads();
#pragma unroll
    for (int i = 0; i < 4; i++) {
        int r = ty * 4 + i;
        size_t go = (size_t)(row0 + r) * DD + tx * 8;
        float4 lo = make_float4(acc[i][0], acc[i][1], acc[i][2], acc[i][3]);
        float4 hi = make_float4(acc[i][4], acc[i][5], acc[i][6], acc[i][7]);
        *reinterpret_cast<float4*>(sV + r * 132 + tx * 8) = lo;
        *reinterpret_cast<float4*>(sV + r * 132 + tx * 8 + 4) = hi;
        *reinterpret_cast<float4*>(g_v + go) = lo;
        *reinterpret_cast<float4*>(g_v + go + 4) = hi;
        store_half8(g_vh + go, acc[i], 1.0f);
    }
    load_wt(Wk, sWt, tid);
    __syncthreads();

    gemm_64x128(sV, sWt, ty, tx, acc);
#pragma unroll
    for (int i = 0; i < 4; i++) {
        size_t go = (size_t)(row0 + ty * 4 + i) * DD + tx * 8;
        store_half8(g_kh + go, acc[i], 1.0f);
    }
    __syncthreads();
    load_wt(Wq, sWt, tid);
    __syncthreads();

    gemm_64x128(sV, sWt, ty, tx, acc);
#pragma unroll
    for (int i = 0; i < 4; i++) {
        size_t go = (size_t)(row0 + ty * 4 + i) * DD + tx * 8;
        store_half8(g_qh + go, acc[i], inv_s);   // pre-scaled q
    }
}

// ---------------- fp16 tensor-core flash attention (race-fixed, round 15) ---
#define HQS 136
#define HKS 136
#define HVS 136
#define HPS 72
#define ATTN_SMEM ((64*HQS + 2*64*HKS + 2*64*HVS + 64*HPS) * 2 + 512 * 4)

__global__ __launch_bounds__(256) void attn_kernel(const int* __restrict__ mask) {
    extern __shared__ __half hsm[];
    __half* sQ = hsm;                         // 64 x 136
    __half* sK = sQ + 64 * HQS;               // 2 x 64 x 136
    __half* sV = sK + 2 * 64 * HKS;           // 2 x 64 x 136
    __half* sP = sV + 2 * 64 * HVS;           // 64 x 72
    float* sM = reinterpret_cast<float*>(sP + 64 * HPS);  // 2 x 64
    float* sL = sM + 128;                     // 2 x 64
    float* sRMax = sL + 128;                  // 64 x 2
    float* sRSum = sRMax + 128;               // 64 x 2

    int tid = threadIdx.x;
    int b = blockIdx.y;
    int n0 = blockIdx.x * 64;
    int w = tid >> 5, lane = tid & 31;
    int mi = w & 3, ni = w >> 2;
    int qg = lane >> 2, qt = lane & 3;
    const float inv_s = 0.088388347648318447f;

    unsigned uQ = smem_u32(sQ);
    unsigned uK = smem_u32(sK);
    unsigned uV = smem_u32(sV);
    unsigned uP = smem_u32(sP);
    int l15 = lane & 15, l7 = lane & 7;

    // ---- load Q tile (fp16, already pre-scaled) ----
    for (int it = tid; it < 64 * 16; it += 256) {
        int r = it >> 4, c8 = it & 15;
        uint4 v = *reinterpret_cast<const uint4*>(
            g_qh + ((size_t)(b * NN + n0 + r)) * DD + c8 * 8);
        *reinterpret_cast<uint4*>(sQ + r * HQS + c8 * 8) = v;
    }
    if (tid < 64) { sM[tid] = -1e30f; sL[tid] = 0.f; }

    // ---- prologue: cp.async tile 0 into buffer 0 ----
    {
        const __half* kb = g_kh + ((size_t)(b * NN)) * DD;
        const __half* vb = g_vh + ((size_t)(b * NN)) * DD;
        for (int it = tid; it < 1024; it += 256) {
            int r = it >> 4, c16 = it & 15;
            cp16(uK + (r * HKS + c16 * 8) * 2, kb + r * DD + c16 * 8);
            cp16(uV + (r * HVS + c16 * 8) * 2, vb + r * DD + c16 * 8);
        }
        asm volatile("cp.async.commit_group;");
    }

    int lr0 = mi * 16 + qg, lr1 = lr0 + 8;

    float acc_o[8][4];
#pragma unroll
    for (int i = 0; i < 8; i++)
#pragma unroll
        for (int j = 0; j < 4; j++) acc_o[i][j] = 0.f;

    for (int t = 0; t < 16; t++) {
        int p = t & 1;
        int m0 = t * 64;
        unsigned uKb = uK + p * (64 * HKS * 2);
        unsigned uVb = uV + p * (64 * HVS * 2);

        // RACE FIX: all warps must be done with the previous iteration's reads
        // of buffer q2 before any warp overwrites it via cp.async.
        __syncthreads();

        // prefetch tile t+1 into other buffer, then wait for tile t
        if (t < 15) {
            int q2 = 1 - p;
            const __half* kb = g_kh + ((size_t)(b * NN + m0 + 64)) * DD;
            const __half* vb = g_vh + ((size_t)(b * NN + m0 + 64)) * DD;
            unsigned dK = uK + q2 * (64 * HKS * 2);
            unsigned dV = uV + q2 * (64 * HVS * 2);
            for (int it = tid; it < 1024; it += 256) {
                int r = it >> 4, c16 = it & 15;
                cp16(dK + (r * HKS + c16 * 8) * 2, kb + r * DD + c16 * 8);
                cp16(dV + (r * HVS + c16 * 8) * 2, vb + r * DD + c16 * 8);
            }
            asm volatile("cp.async.commit_group;");
            asm volatile("cp.async.wait_group 1;");
        } else {
            asm volatile("cp.async.wait_group 0;");
        }
        __syncthreads();   // tile t K/V visible to all warps

        // ---- prefetch kpe/mask rows (overlaps S mma) ----
        const float* kp0 = g_kpe + (size_t)(n0 + lr0) * NN + m0 + ni * 32;
        const float* kp1 = g_kpe + (size_t)(n0 + lr1) * NN + m0 + ni * 32;
        const int* mr0 = mask + ((size_t)b * NN + n0 + lr0) * NN + m0 + ni * 32;
        const int* mr1 = mask + ((size_t)b * NN + n0 + lr1) * NN + m0 + ni * 32;
        float2 kv0[4], kv1[4];
        int2 mv0[4], mv1[4];
#pragma unroll
        for (int nt = 0; nt < 4; nt++) {
            int c = nt * 8 + 2 * qt;
            kv0[nt] = *reinterpret_cast<const float2*>(kp0 + c);
            kv1[nt] = *reinterpret_cast<const float2*>(kp1 + c);
            mv0[nt] = *reinterpret_cast<const int2*>(mr0 + c);
            mv1[nt] = *reinterpret_cast<const int2*>(mr1 + c);
        }

        // ---- S = Q K^T : warp tile 16x32, fp16 m16n8k16 ----
        float acc_s[4][4];
#pragma unroll
        for (int i = 0; i < 4; i++)
#pragma unroll
            for (int j = 0; j < 4; j++) acc_s[i][j] = 0.f;
#pragma unroll
        for (int ks = 0; ks < 8; ks++) {
            unsigned a[4];
            ldsm_x4(a[0], a[1], a[2], a[3],
                    uQ + ((mi * 16 + l15) * HQS + ks * 16 + (lane >> 4) * 8) * 2);
#pragma unroll
            for (int nt = 0; nt < 4; nt++) {
                unsigned bf[2];
                ldsm_x2(bf[0], bf[1],
                        uKb + ((ni * 32 + nt * 8 + l7) * HKS + ks * 16 +
                               ((lane >> 3) & 1) * 8) * 2);
                mma_f16(acc_s[nt], a, bf);
            }
        }

        // ---- + kpe/sqrt(D), mask; segment max ----
        float lmax0 = -1e30f, lmax1 = -1e30f;
#pragma unroll
        for (int nt = 0; nt < 4; nt++) {
            float e00 = acc_s[nt][0] + kv0[nt].x * inv_s; if (mv0[nt].x == 0) e00 = -1e30f;
            float e01 = acc_s[nt][1] + kv0[nt].y * inv_s; if (mv0[nt].y == 0) e01 = -1e30f;
            acc_s[nt][0] = e00; acc_s[nt][1] = e01;
            lmax0 = fmaxf(lmax0, fmaxf(e00, e01));
            float e10 = acc_s[nt][2] + kv1[nt].x * inv_s; if (mv1[nt].x == 0) e10 = -1e30f;
            float e11 = acc_s[nt][3] + kv1[nt].y * inv_s; if (mv1[nt].y == 0) e11 = -1e30f;
            acc_s[nt][2] = e10; acc_s[nt][3] = e11;
            lmax1 = fmaxf(lmax1, fmaxf(e10, e11));
        }
        lmax0 = fmaxf(lmax0, __shfl_xor_sync(0xffffffffu, lmax0, 1));
        lmax0 = fmaxf(lmax0, __shfl_xor_sync(0xffffffffu, lmax0, 2));
        lmax1 = fmaxf(lmax1, __shfl_xor_sync(0xffffffffu, lmax1, 1));
        lmax1 = fmaxf(lmax1, __shfl_xor_sync(0xffffffffu, lmax1, 2));
        if (qt == 0) {
            sRMax[lr0 * 2 + ni] = lmax0;
            sRMax[lr1 * 2 + ni] = lmax1;
        }
        __syncthreads();

        // ---- online softmax; write P (fp16) ----
        float mo0 = sM[p * 64 + lr0], mo1 = sM[p * 64 + lr1];
        float mn0 = fmaxf(mo0, fmaxf(sRMax[lr0 * 2], sRMax[lr0 * 2 + 1]));
        float mn1 = fmaxf(mo1, fmaxf(sRMax[lr1 * 2], sRMax[lr1 * 2 + 1]));
        float f0 = __expf(mo0 - mn0), f1 = __expf(mo1 - mn1);
        float ls0 = 0.f, ls1 = 0.f;
#pragma unroll
        for (int nt = 0; nt < 4; nt++) {
            int c = ni * 32 + nt * 8 + 2 * qt;
            float p00 = (acc_s[nt][0] < -5e29f) ? 0.f : __expf(acc_s[nt][0] - mn0);
            float p01 = (acc_s[nt][1] < -5e29f) ? 0.f : __expf(acc_s[nt][1] - mn0);
            *reinterpret_cast<__half2*>(sP + lr0 * HPS + c) = __floats2half2_rn(p00, p01);
            ls0 += p00 + p01;
            float p10 = (acc_s[nt][2] < -5e29f) ? 0.f : __expf(acc_s[nt][2] - mn1);
            float p11 = (acc_s[nt][3] < -5e29f) ? 0.f : __expf(acc_s[nt][3] - mn1);
            *reinterpret_cast<__half2*>(sP + lr1 * HPS + c) = __floats2half2_rn(p10, p11);
            ls1 += p10 + p11;
        }
        ls0 += __shfl_xor_sync(0xffffffffu, ls0, 1);
        ls0 += __shfl_xor_sync(0xffffffffu, ls0, 2);
        ls1 += __shfl_xor_sync(0xffffffffu, ls1, 1);
        ls1 += __shfl_xor_sync(0xffffffffu, ls1, 2);
        if (qt == 0) {
            sRSum[lr0 * 2 + ni] = ls0;
            sRSum[lr1 * 2 + ni] = ls1;
        }
        // rescale O accumulators
#pragma unroll
        for (int nt = 0; nt < 8; nt++) {
            acc_o[nt][0] *= f0; acc_o[nt][1] *= f0;
            acc_o[nt][2] *= f1; acc_o[nt][3] *= f1;
        }
        __syncthreads();  // sP + sRSum complete

        if (ni == 0 && qt == 0) {
            int q2 = 1 - p;
            sM[q2 * 64 + lr0] = mn0;
            sL[q2 * 64 + lr0] = sL[p * 64 + lr0] * f0 + sRSum[lr0 * 2] + sRSum[lr0 * 2 + 1];
            sM[q2 * 64 + lr1] = mn1;
            sL[q2 * 64 + lr1] = sL[p * 64 + lr1] * f1 + sRSum[lr1 * 2] + sRSum[lr1 * 2 + 1];
        }

        // ---- O += P V : warp tile 16x64, fp16 m16n8k16, V via ldmatrix.trans ----
#pragma unroll
        for (int ks = 0; ks < 4; ks++) {
            unsigned a[4];
            ldsm_x4(a[0], a[1], a[2], a[3],
                    uP + ((mi * 16 + l15) * HPS + ks * 16 + (lane >> 4) * 8) * 2);
#pragma unroll
            for (int nt = 0; nt < 8; nt++) {
                unsigned bf[2];
                ldsm_x2t(bf[0], bf[1],
                         uVb + ((ks * 16 + l15) * HVS + ni * 64 + nt * 8) * 2);
                mma_f16(acc_o[nt], a, bf);
            }
        }
    }

    __syncthreads();  // final sM/sL (parity 0 after t=15) visible
    float il0 = 1.0f / sL[lr0];
    float il1 = 1.0f / sL[lr1];
    float* o0 = g_o + ((size_t)(b * NN + n0 + lr0)) * DD;
    float* o1 = g_o + ((size_t)(b * NN + n0 + lr1)) * DD;
#pragma unroll
    for (int nt = 0; nt < 8; nt++) {
        int c = ni * 64 + nt * 8 + 2 * qt;
        *reinterpret_cast<float2*>(o0 + c) =
            make_float2(acc_o[nt][0] * il0, acc_o[nt][1] * il0);
        *reinterpret_cast<float2*>(o1 + c) =
            make_float2(acc_o[nt][2] * il1, acc_o[nt][3] * il1);
    }
}

// ---------------- epilogue: out = LN(O + vpe) + v ---------------------------
__global__ __launch_bounds__(256) void epi_kernel(
    const float* __restrict__ gamma, const float* __restrict__ beta,
    float* __restrict__ out) {
    int tid = threadIdx.x;
    int b = blockIdx.y;
    int n = blockIdx.x * 64 + (tid >> 2);
    int part = tid & 3;

    const float* orow = g_o + ((size_t)(b * NN + n)) * DD;
    const float* vper = g_vpe + n * DD;
    float x[32];
    float sum = 0.f, sq = 0.f;
#pragma unroll
    for (int u = 0; u < 32; u += 4) {
        int d = part * 32 + u;
        float4 o4 = *reinterpret_cast<const float4*>(orow + d);
        float4 p4 = *reinterpret_cast<const float4*>(vper + d);
        float4 v;
        v.x = o4.x + p4.x; v.y = o4.y + p4.y;
        v.z = o4.z + p4.z; v.w = o4.w + p4.w;
        x[u] = v.x; x[u + 1] = v.y; x[u + 2] = v.z; x[u + 3] = v.w;
        sum += v.x + v.y + v.z + v.w;
        sq += v.x * v.x + v.y * v.y + v.z * v.z + v.w * v.w;
    }
#pragma unroll
    for (int o = 1; o <= 2; o <<= 1) {
        sum += __shfl_xor_sync(0xffffffffu, sum, o);
        sq += __shfl_xor_sync(0xffffffffu, sq, o);
    }
    float mu = sum * (1.f / 128.f);
    float var = sq * (1.f / 128.f) - mu * mu;
    float rstd = rsqrtf(var + 1e-5f);
    const float* gvr = g_v + ((size_t)(b * NN + n)) * DD;
    float* orow_out = out + ((size_t)(b * NN + n)) * DD;
#pragma unroll
    for (int u = 0; u < 32; u += 4) {
        int d = part * 32 + u;
        float4 gm = *reinterpret_cast<const float4*>(gamma + d);
        float4 bt = *reinterpret_cast<const float4*>(beta + d);
        float4 vv = *reinterpret_cast<const float4*>(gvr + d);
        float4 r4;
        r4.x = (x[u] - mu) * rstd * gm.x + bt.x + vv.x;
        r4.y = (x[u + 1] - mu) * rstd * gm.y + bt.y + vv.y;
        r4.z = (x[u + 2] - mu) * rstd * gm.z + bt.z + vv.z;
        r4.w = (x[u + 3] - mu) * rstd * gm.w + bt.w + vv.w;
        *reinterpret_cast<float4*>(orow_out + d) = r4;
    }
}

// ---------------- launch ---------------------------------------------------
extern "C" void kernel_launch(void* const* d_in, const int* in_sizes, int n_in,
                              void* d_out, int out_size) {
    const float* values = (const float*)d_in[0];
    const int* mask = (const int*)d_in[3];
    const float* vpe = (const float*)d_in[4];
    const float* kpe = (const float*)d_in[5];
    const float* Wv = (const float*)d_in[6];
    const float* Wk = (const float*)d_in[7];
    const float* Wq = (const float*)d_in[8];
    const float* ln_gamma = (const float*)d_in[9];
    const float* ln_beta = (const float*)d_in[10];
    float* out = (float*)d_out;

    static cudaStream_t s2 = nullptr;
    static cudaEvent_t ev_fork = nullptr, ev_kpe = nullptr, ev_vpe = nullptr;
    if (!s2) {
        cudaStreamCreateWithFlags(&s2, cudaStreamNonBlocking);   // default priority
        cudaEventCreateWithFlags(&ev_fork, cudaEventDisableTiming);
        cudaEventCreateWithFlags(&ev_kpe, cudaEventDisableTiming);
        cudaEventCreateWithFlags(&ev_vpe, cudaEventDisableTiming);
        cudaFuncSetAttribute(proj_fused_kernel,
                             cudaFuncAttributeMaxDynamicSharedMemorySize, FPROJ_SMEM);
        cudaFuncSetAttribute(attn_kernel,
                             cudaFuncAttributeMaxDynamicSharedMemorySize, ATTN_SMEM);
    }

    // s2: kpe -> vpe (single launches)
    // s0: proj -> (kpe) attn -> (vpe) epi
    cudaEventRecord(ev_fork, 0);
    cudaStreamWaitEvent(s2, ev_fork, 0);
    kpe_kernel<<<NN * NN / 256, 256, 0, s2>>>(kpe);
    cudaEventRecord(ev_kpe, s2);
    vpe_kernel<<<NN, 256, 0, s2>>>(vpe);
    cudaEventRecord(ev_vpe, s2);

    proj_fused_kernel<<<BB * NN / 64, 256, FPROJ_SMEM>>>(values, Wv, Wk, Wq);
    cudaStreamWaitEvent(0, ev_kpe, 0);
    attn_kernel<<<dim3(NN / 64, BB), 256, ATTN_SMEM>>>(mask);
    cudaStreamWaitEvent(0, ev_vpe, 0);
    epi_kernel<<<dim3(NN / 64, BB), 256>>>(ln_gamma, ln_beta, out);
}

// round 17
// speedup vs baseline: 1.1661x; 1.0301x over previous
#include <cuda_runtime.h>
#include <cuda_fp16.h>

#define BB 8
#define NN 1024
#define DD 128

// ---------------- scratch (device globals; no allocation allowed) ----------
__device__ float g_v[BB * NN * DD];
__device__ float g_o[BB * NN * DD];
__device__ __half g_vh[BB * NN * DD];
__device__ __half g_kh[BB * NN * DD];
__device__ __half g_qh[BB * NN * DD];   // pre-scaled by 1/sqrt(D)
__device__ float g_kpe[NN * NN];
__device__ float g_vpe[NN * DD];

// ---------------- asm helpers ----------------------------------------------
__device__ __forceinline__ unsigned smem_u32(const void* p) {
    unsigned a;
    asm("{ .reg .u64 t; cvta.to.shared.u64 t, %1; cvt.u32.u64 %0, t; }"
        : "=r"(a) : "l"(p));
    return a;
}
__device__ __forceinline__ void ldsm_x4(unsigned& a0, unsigned& a1,
                                        unsigned& a2, unsigned& a3, unsigned addr) {
    asm volatile("ldmatrix.sync.aligned.m8n8.x4.shared.b16 {%0,%1,%2,%3}, [%4];"
                 : "=r"(a0), "=r"(a1), "=r"(a2), "=r"(a3) : "r"(addr));
}
__device__ __forceinline__ void ldsm_x2(unsigned& b0, unsigned& b1, unsigned addr) {
    asm volatile("ldmatrix.sync.aligned.m8n8.x2.shared.b16 {%0,%1}, [%2];"
                 : "=r"(b0), "=r"(b1) : "r"(addr));
}
__device__ __forceinline__ void ldsm_x2t(unsigned& b0, unsigned& b1, unsigned addr) {
    asm volatile("ldmatrix.sync.aligned.m8n8.x2.trans.shared.b16 {%0,%1}, [%2];"
                 : "=r"(b0), "=r"(b1) : "r"(addr));
}
__device__ __forceinline__ void mma_f16(float d[4], const unsigned a[4],
                                        const unsigned b[2]) {
    asm("mma.sync.aligned.m16n8k16.row.col.f32.f16.f16.f32 "
        "{%0,%1,%2,%3}, {%4,%5,%6,%7}, {%8,%9}, {%0,%1,%2,%3};"
        : "+f"(d[0]), "+f"(d[1]), "+f"(d[2]), "+f"(d[3])
        : "r"(a[0]), "r"(a[1]), "r"(a[2]), "r"(a[3]), "r"(b[0]), "r"(b[1]));
}
__device__ __forceinline__ void cp16(unsigned dst, const void* src) {
    asm volatile("cp.async.cg.shared.global [%0], [%1], 16;"
                 :: "r"(dst), "l"(src));
}
__device__ __forceinline__ float4 ldcs4(const float4* p) {
    float4 v;
    asm volatile("ld.global.cs.v4.f32 {%0,%1,%2,%3}, [%4];"
                 : "=f"(v.x), "=f"(v.y), "=f"(v.z), "=f"(v.w) : "l"(p));
    return v;
}

// ---------------- kpe[n,m] = sum_d keys_pos_enc[n,m,d] ---------------------
// warp-per-32-rows, software-pipelined (round 16): next group's loads issue
// before this group's shuffle tree. Coalesced 512B rows, streaming loads.
__global__ __launch_bounds__(256) void kpe_kernel(const float* __restrict__ kp) {
    int gwarp = (blockIdx.x * 256 + threadIdx.x) >> 5;
    int lane = threadIdx.x & 31;
    const float4* base = reinterpret_cast<const float4*>(kp)
                         + (size_t)gwarp * 32 * 32 + lane;
    float4 v[8];
#pragma unroll
    for (int i = 0; i < 8; i++) v[i] = ldcs4(base + i * 32);   // group 0 in flight
#pragma unroll
    for (int g = 0; g < 4; g++) {
        float s[8];
#pragma unroll
        for (int i = 0; i < 8; i++)
            s[i] = (v[i].x + v[i].y) + (v[i].z + v[i].w);
        if (g < 3) {   // issue next group's loads before the shuffle phase
#pragma unroll
            for (int i = 0; i < 8; i++)
                v[i] = ldcs4(base + (g + 1) * 8 * 32 + i * 32);
        }
#pragma unroll
        for (int i = 0; i < 8; i++) {
#pragma unroll
            for (int o = 16; o >= 1; o >>= 1)
                s[i] += __shfl_xor_sync(0xffffffffu, s[i], o);
        }
        float out = 0.f;
#pragma unroll
        for (int i = 0; i < 8; i++)
            if (lane == i) out = s[i];
        if (lane < 8) g_kpe[(size_t)gwarp * 32 + g * 8 + lane] = out;
    }
}

// ---------------- vpe[n,d] = sum_m values_pos_enc[n,m,d] -------------------
// single launch (1024 CTAs), 8 independent acc chains, streaming loads.
__global__ void vpe_kernel(const float* __restrict__ vp) {
    __shared__ float4 red[8][32];
    int n = blockIdx.x;
    int g = threadIdx.x >> 5, lane = threadIdx.x & 31;
    const float4* base = reinterpret_cast<const float4*>(vp + (size_t)n * NN * DD);
    float4 acc[8];
#pragma unroll
    for (int i = 0; i < 8; i++) acc[i] = make_float4(0.f, 0.f, 0.f, 0.f);
    for (int m = g; m < NN; m += 64) {
#pragma unroll
        for (int i = 0; i < 8; i++) {
            float4 v = ldcs4(base + (m + i * 8) * 32 + lane);
            acc[i].x += v.x; acc[i].y += v.y; acc[i].z += v.z; acc[i].w += v.w;
        }
    }
#pragma unroll
    for (int i = 1; i < 8; i++) {
        acc[0].x += acc[i].x; acc[0].y += acc[i].y;
        acc[0].z += acc[i].z; acc[0].w += acc[i].w;
    }
    red[g][lane] = acc[0];
    __syncthreads();
    if (g == 0) {
        float4 a = red[0][lane];
#pragma unroll
        for (int i = 1; i < 8; i++) {
            float4 b = red[i][lane];
            a.x += b.x; a.y += b.y; a.z += b.z; a.w += b.w;
        }
        reinterpret_cast<float4*>(g_vpe + n * DD)[lane] = a;
    }
}

// ---------------- fused projection: v = X Wv^T; k = v Wk^T; q = v Wq^T -----
#define FPROJ_SMEM ((64 * 132 + 64 * 132 + 128 * 132) * 4)

__device__ __forceinline__ void gemm_64x128(const float* __restrict__ sA,
                                            const float* __restrict__ sWt,
                                            int ty, int tx, float acc[4][8]) {
#pragma unroll
    for (int i = 0; i < 4; i++)
#pragma unroll
        for (int j = 0; j < 8; j++) acc[i][j] = 0.f;
    for (int kk = 0; kk < 128; kk += 4) {
        float4 a[4];
#pragma unroll
        for (int i = 0; i < 4; i++)
            a[i] = *reinterpret_cast<const float4*>(sA + (ty * 4 + i) * 132 + kk);
#pragma unroll
        for (int t = 0; t < 4; t++) {
            float4 b0 = *reinterpret_cast<const float4*>(sWt + (kk + t) * 132 + tx * 8);
            float4 b1 = *reinterpret_cast<const float4*>(sWt + (kk + t) * 132 + tx * 8 + 4);
#pragma unroll
            for (int i = 0; i < 4; i++) {
                float aa = reinterpret_cast<const float*>(&a[i])[t];
                acc[i][0] += aa * b0.x; acc[i][1] += aa * b0.y;
                acc[i][2] += aa * b0.z; acc[i][3] += aa * b0.w;
                acc[i][4] += aa * b1.x; acc[i][5] += aa * b1.y;
                acc[i][6] += aa * b1.z; acc[i][7] += aa * b1.w;
            }
        }
    }
}

__device__ __forceinline__ void load_wt(const float* __restrict__ W,
                                        float* __restrict__ sWt, int tid) {
    for (int it = tid; it < 128 * 32; it += 256) {
        int o = it >> 5, e4 = it & 31;
        float4 v = *reinterpret_cast<const float4*>(W + o * DD + e4 * 4);
        sWt[(e4 * 4 + 0) * 132 + o] = v.x;
        sWt[(e4 * 4 + 1) * 132 + o] = v.y;
        sWt[(e4 * 4 + 2) * 132 + o] = v.z;
        sWt[(e4 * 4 + 3) * 132 + o] = v.w;
    }
}

__device__ __forceinline__ void store_half8(__half* dst, const float* a, float sc) {
#pragma unroll
    for (int j = 0; j < 4; j++) {
        __half2 h = __floats2half2_rn(a[2 * j] * sc, a[2 * j + 1] * sc);
        *reinterpret_cast<__half2*>(dst + 2 * j) = h;
    }
}

__global__ __launch_bounds__(256) void proj_fused_kernel(
    const float* __restrict__ X, const float* __restrict__ Wv,
    const float* __restrict__ Wk, const float* __restrict__ Wq) {
    extern __shared__ float sm[];
    float* sX = sm;
    float* sV = sm + 64 * 132;
    float* sWt = sm + 2 * 64 * 132;
    const float inv_s = 0.088388347648318447f;

    int tid = threadIdx.x;
    int row0 = blockIdx.x * 64;
    int ty = tid >> 4, tx = tid & 15;
    float acc[4][8];

    for (int it = tid; it < 64 * 32; it += 256) {
        int r = it >> 5, c4 = it & 31;
        float4 v = *reinterpret_cast<const float4*>(X + (size_t)(row0 + r) * DD + c4 * 4);
        *reinterpret_cast<float4*>(sX + r * 132 + c4 * 4) = v;
    }
    load_wt(Wv, sWt, tid);
    __syncthreads();

    gemm_64x128(sX, sWt, ty, tx, acc);
    __syncthreads();
#pragma unroll
    for (int i = 0; i < 4; i++) {
        int r = ty * 4 + i;
        size_t go = (size_t)(row0 + r) * DD + tx * 8;
        float4 lo = make_float4(acc[i][0], acc[i][1], acc[i][2], acc[i][3]);
        float4 hi = make_float4(acc[i][4], acc[i][5], acc[i][6], acc[i][7]);
        *reinterpret_cast<float4*>(sV + r * 132 + tx * 8) = lo;
        *reinterpret_cast<float4*>(sV + r * 132 + tx * 8 + 4) = hi;
        *reinterpret_cast<float4*>(g_v + go) = lo;
        *reinterpret_cast<float4*>(g_v + go + 4) = hi;
        store_half8(g_vh + go, acc[i], 1.0f);
    }
    load_wt(Wk, sWt, tid);
    __syncthreads();

    gemm_64x128(sV, sWt, ty, tx, acc);
#pragma unroll
    for (int i = 0; i < 4; i++) {
        size_t go = (size_t)(row0 + ty * 4 + i) * DD + tx * 8;
        store_half8(g_kh + go, acc[i], 1.0f);
    }
    __syncthreads();
    load_wt(Wq, sWt, tid);
    __syncthreads();

    gemm_64x128(sV, sWt, ty, tx, acc);
#pragma unroll
    for (int i = 0; i < 4; i++) {
        size_t go = (size_t)(row0 + ty * 4 + i) * DD + tx * 8;
        store_half8(g_qh + go, acc[i], inv_s);   // pre-scaled q
    }
}

// ---------------- fp16 tensor-core flash attention (race-fixed, round 15) ---
#define HQS 136
#define HKS 136
#define HVS 136
#define HPS 72
#define ATTN_SMEM ((64*HQS + 2*64*HKS + 2*64*HVS + 64*HPS) * 2 + 512 * 4)

__global__ __launch_bounds__(256) void attn_kernel(const int* __restrict__ mask) {
    extern __shared__ __half hsm[];
    __half* sQ = hsm;                         // 64 x 136
    __half* sK = sQ + 64 * HQS;               // 2 x 64 x 136
    __half* sV = sK + 2 * 64 * HKS;           // 2 x 64 x 136
    __half* sP = sV + 2 * 64 * HVS;           // 64 x 72
    float* sM = reinterpret_cast<float*>(sP + 64 * HPS);  // 2 x 64
    float* sL = sM + 128;                     // 2 x 64
    float* sRMax = sL + 128;                  // 64 x 2
    float* sRSum = sRMax + 128;               // 64 x 2

    int tid = threadIdx.x;
    int b = blockIdx.y;
    int n0 = blockIdx.x * 64;
    int w = tid >> 5, lane = tid & 31;
    int mi = w & 3, ni = w >> 2;
    int qg = lane >> 2, qt = lane & 3;
    const float inv_s = 0.088388347648318447f;

    unsigned uQ = smem_u32(sQ);
    unsigned uK = smem_u32(sK);
    unsigned uV = smem_u32(sV);
    unsigned uP = smem_u32(sP);
    int l15 = lane & 15, l7 = lane & 7;

    // ---- load Q tile (fp16, already pre-scaled) ----
    for (int it = tid; it < 64 * 16; it += 256) {
        int r = it >> 4, c8 = it & 15;
        uint4 v = *reinterpret_cast<const uint4*>(
            g_qh + ((size_t)(b * NN + n0 + r)) * DD + c8 * 8);
        *reinterpret_cast<uint4*>(sQ + r * HQS + c8 * 8) = v;
    }
    if (tid < 64) { sM[tid] = -1e30f; sL[tid] = 0.f; }

    // ---- prologue: cp.async tile 0 into buffer 0 ----
    {
        const __half* kb = g_kh + ((size_t)(b * NN)) * DD;
        const __half* vb = g_vh + ((size_t)(b * NN)) * DD;
        for (int it = tid; it < 1024; it += 256) {
            int r = it >> 4, c16 = it & 15;
            cp16(uK + (r * HKS + c16 * 8) * 2, kb + r * DD + c16 * 8);
            cp16(uV + (r * HVS + c16 * 8) * 2, vb + r * DD + c16 * 8);
        }
        asm volatile("cp.async.commit_group;");
    }

    int lr0 = mi * 16 + qg, lr1 = lr0 + 8;

    float acc_o[8][4];
#pragma unroll
    for (int i = 0; i < 8; i++)
#pragma unroll
        for (int j = 0; j < 4; j++) acc_o[i][j] = 0.f;

    for (int t = 0; t < 16; t++) {
        int p = t & 1;
        int m0 = t * 64;
        unsigned uKb = uK + p * (64 * HKS * 2);
        unsigned uVb = uV + p * (64 * HVS * 2);

        // RACE FIX: all warps must be done with the previous iteration's reads
        // of buffer q2 before any warp overwrites it via cp.async.
        __syncthreads();

        // prefetch tile t+1 into other buffer, then wait for tile t
        if (t < 15) {
            int q2 = 1 - p;
            const __half* kb = g_kh + ((size_t)(b * NN + m0 + 64)) * DD;
            const __half* vb = g_vh + ((size_t)(b * NN + m0 + 64)) * DD;
            unsigned dK = uK + q2 * (64 * HKS * 2);
            unsigned dV = uV + q2 * (64 * HVS * 2);
            for (int it = tid; it < 1024; it += 256) {
                int r = it >> 4, c16 = it & 15;
                cp16(dK + (r * HKS + c16 * 8) * 2, kb + r * DD + c16 * 8);
                cp16(dV + (r * HVS + c16 * 8) * 2, vb + r * DD + c16 * 8);
            }
            asm volatile("cp.async.commit_group;");
            asm volatile("cp.async.wait_group 1;");
        } else {
            asm volatile("cp.async.wait_group 0;");
        }
        __syncthreads();   // tile t K/V visible to all warps

        // ---- prefetch kpe/mask rows (overlaps S mma) ----
        const float* kp0 = g_kpe + (size_t)(n0 + lr0) * NN + m0 + ni * 32;
        const float* kp1 = g_kpe + (size_t)(n0 + lr1) * NN + m0 + ni * 32;
        const int* mr0 = mask + ((size_t)b * NN + n0 + lr0) * NN + m0 + ni * 32;
        const int* mr1 = mask + ((size_t)b * NN + n0 + lr1) * NN + m0 + ni * 32;
        float2 kv0[4], kv1[4];
        int2 mv0[4], mv1[4];
#pragma unroll
        for (int nt = 0; nt < 4; nt++) {
            int c = nt * 8 + 2 * qt;
            kv0[nt] = *reinterpret_cast<const float2*>(kp0 + c);
            kv1[nt] = *reinterpret_cast<const float2*>(kp1 + c);
            mv0[nt] = *reinterpret_cast<const int2*>(mr0 + c);
            mv1[nt] = *reinterpret_cast<const int2*>(mr1 + c);
        }

        // ---- S = Q K^T : warp tile 16x32, fp16 m16n8k16 ----
        float acc_s[4][4];
#pragma unroll
        for (int i = 0; i < 4; i++)
#pragma unroll
            for (int j = 0; j < 4; j++) acc_s[i][j] = 0.f;
#pragma unroll
        for (int ks = 0; ks < 8; ks++) {
            unsigned a[4];
            ldsm_x4(a[0], a[1], a[2], a[3],
                    uQ + ((mi * 16 + l15) * HQS + ks * 16 + (lane >> 4) * 8) * 2);
#pragma unroll
            for (int nt = 0; nt < 4; nt++) {
                unsigned bf[2];
                ldsm_x2(bf[0], bf[1],
                        uKb + ((ni * 32 + nt * 8 + l7) * HKS + ks * 16 +
                               ((lane >> 3) & 1) * 8) * 2);
                mma_f16(acc_s[nt], a, bf);
            }
        }

        // ---- + kpe/sqrt(D), mask; segment max ----
        float lmax0 = -1e30f, lmax1 = -1e30f;
#pragma unroll
        for (int nt = 0; nt < 4; nt++) {
            float e00 = acc_s[nt][0] + kv0[nt].x * inv_s; if (mv0[nt].x == 0) e00 = -1e30f;
            float e01 = acc_s[nt][1] + kv0[nt].y * inv_s; if (mv0[nt].y == 0) e01 = -1e30f;
            acc_s[nt][0] = e00; acc_s[nt][1] = e01;
            lmax0 = fmaxf(lmax0, fmaxf(e00, e01));
            float e10 = acc_s[nt][2] + kv1[nt].x * inv_s; if (mv1[nt].x == 0) e10 = -1e30f;
            float e11 = acc_s[nt][3] + kv1[nt].y * inv_s; if (mv1[nt].y == 0) e11 = -1e30f;
            acc_s[nt][2] = e10; acc_s[nt][3] = e11;
            lmax1 = fmaxf(lmax1, fmaxf(e10, e11));
        }
        lmax0 = fmaxf(lmax0, __shfl_xor_sync(0xffffffffu, lmax0, 1));
        lmax0 = fmaxf(lmax0, __shfl_xor_sync(0xffffffffu, lmax0, 2));
        lmax1 = fmaxf(lmax1, __shfl_xor_sync(0xffffffffu, lmax1, 1));
        lmax1 = fmaxf(lmax1, __shfl_xor_sync(0xffffffffu, lmax1, 2));
        if (qt == 0) {
            sRMax[lr0 * 2 + ni] = lmax0;
            sRMax[lr1 * 2 + ni] = lmax1;
        }
        __syncthreads();

        // ---- online softmax; write P (fp16) ----
        float mo0 = sM[p * 64 + lr0], mo1 = sM[p * 64 + lr1];
        float mn0 = fmaxf(mo0, fmaxf(sRMax[lr0 * 2], sRMax[lr0 * 2 + 1]));
        float mn1 = fmaxf(mo1, fmaxf(sRMax[lr1 * 2], sRMax[lr1 * 2 + 1]));
        float f0 = __expf(mo0 - mn0), f1 = __expf(mo1 - mn1);
        float ls0 = 0.f, ls1 = 0.f;
#pragma unroll
        for (int nt = 0; nt < 4; nt++) {
            int c = ni * 32 + nt * 8 + 2 * qt;
            float p00 = (acc_s[nt][0] < -5e29f) ? 0.f : __expf(acc_s[nt][0] - mn0);
            float p01 = (acc_s[nt][1] < -5e29f) ? 0.f : __expf(acc_s[nt][1] - mn0);
            *reinterpret_cast<__half2*>(sP + lr0 * HPS + c) = __floats2half2_rn(p00, p01);
            ls0 += p00 + p01;
            float p10 = (acc_s[nt][2] < -5e29f) ? 0.f : __expf(acc_s[nt][2] - mn1);
            float p11 = (acc_s[nt][3] < -5e29f) ? 0.f : __expf(acc_s[nt][3] - mn1);
            *reinterpret_cast<__half2*>(sP + lr1 * HPS + c) = __floats2half2_rn(p10, p11);
            ls1 += p10 + p11;
        }
        ls0 += __shfl_xor_sync(0xffffffffu, ls0, 1);
        ls0 += __shfl_xor_sync(0xffffffffu, ls0, 2);
        ls1 += __shfl_xor_sync(0xffffffffu, ls1, 1);
        ls1 += __shfl_xor_sync(0xffffffffu, ls1, 2);
        if (qt == 0) {
            sRSum[lr0 * 2 + ni] = ls0;
            sRSum[lr1 * 2 + ni] = ls1;
        }
        // rescale O accumulators
#pragma unroll
        for (int nt = 0; nt < 8; nt++) {
            acc_o[nt][0] *= f0; acc_o[nt][1] *= f0;
            acc_o[nt][2] *= f1; acc_o[nt][3] *= f1;
        }
        __syncthreads();  // sP + sRSum complete

        if (ni == 0 && qt == 0) {
            int q2 = 1 - p;
            sM[q2 * 64 + lr0] = mn0;
            sL[q2 * 64 + lr0] = sL[p * 64 + lr0] * f0 + sRSum[lr0 * 2] + sRSum[lr0 * 2 + 1];
            sM[q2 * 64 + lr1] = mn1;
            sL[q2 * 64 + lr1] = sL[p * 64 + lr1] * f1 + sRSum[lr1 * 2] + sRSum[lr1 * 2 + 1];
        }

        // ---- O += P V : warp tile 16x64, fp16 m16n8k16, V via ldmatrix.trans ----
#pragma unroll
        for (int ks = 0; ks < 4; ks++) {
            unsigned a[4];
            ldsm_x4(a[0], a[1], a[2], a[3],
                    uP + ((mi * 16 + l15) * HPS + ks * 16 + (lane >> 4) * 8) * 2);
#pragma unroll
            for (int nt = 0; nt < 8; nt++) {
                unsigned bf[2];
                ldsm_x2t(bf[0], bf[1],
                         uVb + ((ks * 16 + l15) * HVS + ni * 64 + nt * 8) * 2);
                mma_f16(acc_o[nt], a, bf);
            }
        }
    }

    __syncthreads();  // final sM/sL (parity 0 after t=15) visible
    float il0 = 1.0f / sL[lr0];
    float il1 = 1.0f / sL[lr1];
    float* o0 = g_o + ((size_t)(b * NN + n0 + lr0)) * DD;
    float* o1 = g_o + ((size_t)(b * NN + n0 + lr1)) * DD;
#pragma unroll
    for (int nt = 0; nt < 8; nt++) {
        int c = ni * 64 + nt * 8 + 2 * qt;
        *reinterpret_cast<float2*>(o0 + c) =
            make_float2(acc_o[nt][0] * il0, acc_o[nt][1] * il0);
        *reinterpret_cast<float2*>(o1 + c) =
            make_float2(acc_o[nt][2] * il1, acc_o[nt][3] * il1);
    }
}

// ---------------- epilogue v2: warp-per-row, out = LN(O + vpe) + v ----------
// one warp owns one (b, n) row: 1 float4 load pair -> 5-level shuffle reduce
// -> LN + residual. 1024 CTAs of 8 warps (vs 128 CTAs, 8-deep serial chains).
__global__ __launch_bounds__(256) void epi_kernel(
    const float* __restrict__ gamma, const float* __restrict__ beta,
    float* __restrict__ out) {
    int wid = threadIdx.x >> 5, lane = threadIdx.x & 31;
    int b = blockIdx.y;
    int n = blockIdx.x * 8 + wid;

    const float* orow = g_o + ((size_t)(b * NN + n)) * DD;
    const float* vper = g_vpe + n * DD;
    int d = lane * 4;
    float4 o4 = *reinterpret_cast<const float4*>(orow + d);
    float4 p4 = *reinterpret_cast<const float4*>(vper + d);
    float4 x;
    x.x = o4.x + p4.x; x.y = o4.y + p4.y;
    x.z = o4.z + p4.z; x.w = o4.w + p4.w;
    float sum = (x.x + x.y) + (x.z + x.w);
    float sq = (x.x * x.x + x.y * x.y) + (x.z * x.z + x.w * x.w);
#pragma unroll
    for (int o = 16; o >= 1; o >>= 1) {
        sum += __shfl_xor_sync(0xffffffffu, sum, o);
        sq += __shfl_xor_sync(0xffffffffu, sq, o);
    }
    float mu = sum * (1.f / 128.f);
    float var = sq * (1.f / 128.f) - mu * mu;
    float rstd = rsqrtf(var + 1e-5f);
    float4 gm = *reinterpret_cast<const float4*>(gamma + d);
    float4 bt = *reinterpret_cast<const float4*>(beta + d);
    float4 vv = *reinterpret_cast<const float4*>(g_v + ((size_t)(b * NN + n)) * DD + d);
    float4 r4;
    r4.x = (x.x - mu) * rstd * gm.x + bt.x + vv.x;
    r4.y = (x.y - mu) * rstd * gm.y + bt.y + vv.y;
    r4.z = (x.z - mu) * rstd * gm.z + bt.z + vv.z;
    r4.w = (x.w - mu) * rstd * gm.w + bt.w + vv.w;
    *reinterpret_cast<float4*>(out + ((size_t)(b * NN + n)) * DD + d) = r4;
}

// ---------------- launch ---------------------------------------------------
extern "C" void kernel_launch(void* const* d_in, const int* in_sizes, int n_in,
                              void* d_out, int out_size) {
    const float* values = (const float*)d_in[0];
    const int* mask = (const int*)d_in[3];
    const float* vpe = (const float*)d_in[4];
    const float* kpe = (const float*)d_in[5];
    const float* Wv = (const float*)d_in[6];
    const float* Wk = (const float*)d_in[7];
    const float* Wq = (const float*)d_in[8];
    const float* ln_gamma = (const float*)d_in[9];
    const float* ln_beta = (const float*)d_in[10];
    float* out = (float*)d_out;

    static cudaStream_t s2 = nullptr;
    static cudaEvent_t ev_fork = nullptr, ev_kpe = nullptr, ev_vpe = nullptr;
    if (!s2) {
        cudaStreamCreateWithFlags(&s2, cudaStreamNonBlocking);   // default priority
        cudaEventCreateWithFlags(&ev_fork, cudaEventDisableTiming);
        cudaEventCreateWithFlags(&ev_kpe, cudaEventDisableTiming);
        cudaEventCreateWithFlags(&ev_vpe, cudaEventDisableTiming);
        cudaFuncSetAttribute(proj_fused_kernel,
                             cudaFuncAttributeMaxDynamicSharedMemorySize, FPROJ_SMEM);
        cudaFuncSetAttribute(attn_kernel,
                             cudaFuncAttributeMaxDynamicSharedMemorySize, ATTN_SMEM);
    }

    // s2: kpe -> vpe (single launches)
    // s0: proj -> (kpe) attn -> (vpe) epi
    cudaEventRecord(ev_fork, 0);
    cudaStreamWaitEvent(s2, ev_fork, 0);
    kpe_kernel<<<NN * NN / 256, 256, 0, s2>>>(kpe);
    cudaEventRecord(ev_kpe, s2);
    vpe_kernel<<<NN, 256, 0, s2>>>(vpe);
    cudaEventRecord(ev_vpe, s2);

    proj_fused_kernel<<<BB * NN / 64, 256, FPROJ_SMEM>>>(values, Wv, Wk, Wq);
    cudaStreamWaitEvent(0, ev_kpe, 0);
    attn_kernel<<<dim3(NN / 64, BB), 256, ATTN_SMEM>>>(mask);
    cudaStreamWaitEvent(0, ev_vpe, 0);
    epi_kernel<<<dim3(NN / 8, BB), 256>>>(ln_gamma, ln_beta, out);
}